// round 1
// baseline (speedup 1.0000x reference)
#include <cuda_runtime.h>
#include <math.h>

// Problem sizes (fixed by reference)
#define BB 1024
#define NN 24
#define LL 24
#define DD 128
#define VV 40000
#define NV 39999      // V-1 output columns
#define ALPHA 0.2f
#define NEGC (-9e15f)

// GEMM tiling
#define TM 64
#define KT 16
#define AST 68        // Asm row stride (floats), 16B-aligned, padded
#define BST 132       // Bsm row stride (floats), 16B-aligned, padded

// -------- device scratch (no allocations allowed) --------
__device__ float g_Wci[DD*DD];
__device__ float g_Wct[DD*DD];
__device__ float g_bcomb[DD];
__device__ float g_h[BB*NN*DD];
__device__ float g_seq[BB*LL*DD];
__device__ float g_nh[BB*LL*DD];
__device__ float g_gate[BB*LL*DD];
__device__ float g_hs[BB*DD];
__device__ float g_hsg[BB*DD];
__device__ float g_select[BB*DD];

// ==================== K0: fold W_img/W_txt into W_fuse ====================
// Wci[k,d] = sum_j W_img[k,j] * W_fuse[128+j, d]
// Wct[k,d] = sum_j W_txt[k,j] * W_fuse[256+j, d]
// bcomb[d] = b_fuse[d] + b_img @ W_fuse[128:256] + b_txt @ W_fuse[256:384]
__global__ void k0_combine(const float* __restrict__ W_img, const float* __restrict__ W_txt,
                           const float* __restrict__ W_fuse, const float* __restrict__ b_img,
                           const float* __restrict__ b_txt, const float* __restrict__ b_fuse) {
    int k = blockIdx.x, d = threadIdx.x;
    float s1 = 0.f, s2 = 0.f;
    for (int j = 0; j < DD; j++) {
        s1 += W_img[k*DD + j] * W_fuse[(DD   + j)*DD + d];
        s2 += W_txt[k*DD + j] * W_fuse[(2*DD + j)*DD + d];
    }
    g_Wci[k*DD + d] = s1;
    g_Wct[k*DD + d] = s2;
    if (k == 0) {
        float s = b_fuse[d];
        for (int j = 0; j < DD; j++) {
            s += b_img[j]*W_fuse[(DD + j)*DD + d] + b_txt[j]*W_fuse[(2*DD + j)*DD + d];
        }
        g_bcomb[d] = s;
    }
}

// ==================== shared GEMM micro-kernel ====================
// 256 threads, 64x128 output tile, acc[4][8] per thread.
__device__ __forceinline__ void mm_step(const float* Asm, const float* Bsm,
                                        float acc[4][8], int tr, int tc) {
#pragma unroll
    for (int kk = 0; kk < KT; kk++) {
        float4 a4 = *reinterpret_cast<const float4*>(&Asm[kk*AST + tr*4]);
        float4 b0 = *reinterpret_cast<const float4*>(&Bsm[kk*BST + tc*8]);
        float4 b1 = *reinterpret_cast<const float4*>(&Bsm[kk*BST + tc*8 + 4]);
        float av[4] = {a4.x, a4.y, a4.z, a4.w};
        float bv[8] = {b0.x, b0.y, b0.z, b0.w, b1.x, b1.y, b1.z, b1.w};
#pragma unroll
        for (int i = 0; i < 4; i++)
#pragma unroll
            for (int j = 0; j < 8; j++) acc[i][j] += av[i]*bv[j];
    }
}

// ==================== K1: fused multimodal embedding ====================
// h[row] = emb[it]@Wfuse[0:128] + img[it]@Wci + txt[it]@Wct + bcomb
__global__ void k1_fuse(const int* __restrict__ items, const float* __restrict__ emb,
                        const float* __restrict__ img, const float* __restrict__ txt,
                        const float* __restrict__ W_fuse) {
    __shared__ float Asm[KT*AST];
    __shared__ float Bsm[KT*BST];
    __shared__ int sitem[TM];
    int tid = threadIdx.x;
    int m0 = blockIdx.x * TM;
    if (tid < TM) sitem[tid] = items[m0 + tid];
    int tc = tid & 15, tr = tid >> 4;
    float acc[4][8] = {};
    __syncthreads();
    for (int kt = 0; kt < 24; kt++) {
        int k0 = kt * KT;
        int seg = k0 >> 7;
        int kl  = k0 & 127;
        const float* src = (seg == 0) ? emb : ((seg == 1) ? img : txt);
        const float* Wp  = (seg == 0) ? W_fuse : ((seg == 1) ? g_Wci : g_Wct);
#pragma unroll
        for (int t = 0; t < 4; t++) {
            int idx = tid + t*256;
            int kk = idx & 15, r = idx >> 4;
            Asm[kk*AST + r] = src[(size_t)sitem[r]*DD + kl + kk];
        }
#pragma unroll
        for (int t = 0; t < 8; t++) {
            int idx = tid + t*256;
            int c = idx & 127, kk = idx >> 7;
            Bsm[kk*BST + c] = Wp[(kl + kk)*DD + c];
        }
        __syncthreads();
        mm_step(Asm, Bsm, acc, tr, tc);
        __syncthreads();
    }
#pragma unroll
    for (int i = 0; i < 4; i++) {
        int row = m0 + tr*4 + i;
#pragma unroll
        for (int j = 0; j < 8; j++) {
            int c = tc*8 + j;
            g_h[(size_t)row*DD + c] = acc[i][j] + g_bcomb[c];
        }
    }
}

// ==================== K2: RGAT attention + seq remap + masked mean ====================
__global__ void k2_attn(const int* __restrict__ adj, const int* __restrict__ alias_,
                        const int* __restrict__ mask_, const float* __restrict__ a_rel) {
    __shared__ float hsm[NN*DD];
    __shared__ float hag[NN*DD];
    __shared__ float logit[NN*NN];
    __shared__ float arel[4*DD];
    __shared__ int salias[LL];
    __shared__ int smask[LL];
    __shared__ float hpart[256];
    int b = blockIdx.x, tid = threadIdx.x;

    for (int idx = tid; idx < NN*DD; idx += 256) hsm[idx] = g_h[(size_t)b*NN*DD + idx];
    for (int idx = tid; idx < 4*DD;  idx += 256) arel[idx] = a_rel[idx];
    if (tid < LL) { salias[tid] = alias_[b*LL + tid]; smask[tid] = mask_[b*LL + tid]; }
    __syncthreads();

    // relation-typed edge scores: 4 threads per (i,j) pair
    int grp = tid >> 2, l4 = tid & 3;
    for (int p = grp; p < NN*NN; p += 64) {
        int i = p / NN, j = p % NN;
        int r = adj[(size_t)b*NN*NN + p];
        int rr = (r >= 1) ? (r - 1) : 0;
        const float* ar = &arel[rr*DD];
        const float* hi = &hsm[i*DD];
        const float* hj = &hsm[j*DD];
        float s = 0.f;
        int d0 = l4 * 32;
        for (int d = d0; d < d0 + 32; d++) s += hi[d]*hj[d]*ar[d];
        s += __shfl_xor_sync(0xffffffffu, s, 1, 4);
        s += __shfl_xor_sync(0xffffffffu, s, 2, 4);
        if (l4 == 0) {
            float e = (s > 0.f) ? s : ALPHA * s;
            logit[p] = (r == 0) ? NEGC : e;
        }
    }
    __syncthreads();

    // row-wise softmax (matches jax: max-subtract; all-masked row -> uniform)
    if (tid < NN) {
        float m = -INFINITY;
        for (int j = 0; j < NN; j++) m = fmaxf(m, logit[tid*NN + j]);
        float ex[NN]; float ssum = 0.f;
        for (int j = 0; j < NN; j++) { ex[j] = expf(logit[tid*NN + j] - m); ssum += ex[j]; }
        float inv = 1.f / ssum;
        for (int j = 0; j < NN; j++) logit[tid*NN + j] = ex[j] * inv;
    }
    __syncthreads();

    // aggregate
    for (int idx = tid; idx < NN*DD; idx += 256) {
        int i = idx >> 7, d = idx & 127;
        float s = 0.f;
        for (int j = 0; j < NN; j++) s += logit[i*NN + j] * hsm[j*DD + d];
        hag[idx] = s;
    }
    __syncthreads();

    // seq = h_agg[alias]; hs = masked mean over L  (d = tid&127 is constant per thread)
    float part = 0.f;
    for (int idx = tid; idx < LL*DD; idx += 256) {
        int l = idx >> 7;
        int d = idx & 127;
        float v = hag[salias[l]*DD + d];
        g_seq[(size_t)b*LL*DD + idx] = v;
        part += v * (float)smask[l];
    }
    hpart[tid] = part;
    __syncthreads();
    if (tid < DD) {
        int ms = 0;
        for (int l = 0; l < LL; l++) ms += smask[l];
        float denom = fmaxf((float)ms, 1.f);
        g_hs[(size_t)b*DD + tid] = (hpart[tid] + hpart[tid + 128]) / denom;
    }
}

// ==================== K3h: hsg = glu1_b + hs @ glu2_w ====================
__global__ void k3_hsg(const float* __restrict__ glu2_w, const float* __restrict__ glu1_b) {
    __shared__ float shs[DD];
    int b = blockIdx.x, d = threadIdx.x;
    shs[d] = g_hs[(size_t)b*DD + d];
    __syncthreads();
    float s = glu1_b[d];
    for (int k = 0; k < DD; k++) s += shs[k] * glu2_w[k*DD + d];
    g_hsg[(size_t)b*DD + d] = s;
}

// ==================== K3a: nh = tanh([pos_rev | seq] @ w_1) ====================
__global__ void k3a_nh(const float* __restrict__ pos_emb, const float* __restrict__ w_1) {
    __shared__ float Asm[KT*AST];
    __shared__ float Bsm[KT*BST];
    int tid = threadIdx.x;
    int m0 = blockIdx.x * TM;
    int tc = tid & 15, tr = tid >> 4;
    float acc[4][8] = {};
    for (int kt = 0; kt < 16; kt++) {
        int k0 = kt * KT;
#pragma unroll
        for (int t = 0; t < 4; t++) {
            int idx = tid + t*256;
            int kk = idx & 15, r = idx >> 4;
            int row = m0 + r;
            float a;
            if (k0 < DD) {
                int l = row % LL;
                a = pos_emb[(LL - 1 - l)*DD + k0 + kk];
            } else {
                a = g_seq[(size_t)row*DD + (k0 - DD) + kk];
            }
            Asm[kk*AST + r] = a;
        }
#pragma unroll
        for (int t = 0; t < 8; t++) {
            int idx = tid + t*256;
            int c = idx & 127, kk = idx >> 7;
            Bsm[kk*BST + c] = w_1[(k0 + kk)*DD + c];
        }
        __syncthreads();
        mm_step(Asm, Bsm, acc, tr, tc);
        __syncthreads();
    }
#pragma unroll
    for (int i = 0; i < 4; i++) {
        int row = m0 + tr*4 + i;
#pragma unroll
        for (int j = 0; j < 8; j++) {
            int c = tc*8 + j;
            g_nh[(size_t)row*DD + c] = tanhf(acc[i][j]);
        }
    }
}

// ==================== K3b: gate = sigmoid(nh @ glu1_w + hsg[b]) ====================
__global__ void k3b_gate(const float* __restrict__ glu1_w) {
    __shared__ float Asm[KT*AST];
    __shared__ float Bsm[KT*BST];
    int tid = threadIdx.x;
    int m0 = blockIdx.x * TM;
    int tc = tid & 15, tr = tid >> 4;
    float acc[4][8] = {};
    for (int kt = 0; kt < 8; kt++) {
        int k0 = kt * KT;
#pragma unroll
        for (int t = 0; t < 4; t++) {
            int idx = tid + t*256;
            int kk = idx & 15, r = idx >> 4;
            Asm[kk*AST + r] = g_nh[(size_t)(m0 + r)*DD + k0 + kk];
        }
#pragma unroll
        for (int t = 0; t < 8; t++) {
            int idx = tid + t*256;
            int c = idx & 127, kk = idx >> 7;
            Bsm[kk*BST + c] = glu1_w[(k0 + kk)*DD + c];
        }
        __syncthreads();
        mm_step(Asm, Bsm, acc, tr, tc);
        __syncthreads();
    }
#pragma unroll
    for (int i = 0; i < 4; i++) {
        int row = m0 + tr*4 + i;
        int b = row / LL;
#pragma unroll
        for (int j = 0; j < 8; j++) {
            int c = tc*8 + j;
            float v = acc[i][j] + g_hsg[(size_t)b*DD + c];
            g_gate[(size_t)row*DD + c] = 1.f / (1.f + expf(-v));
        }
    }
}

// ==================== K3c: beta = gate@w_2 ; select = sum_l beta*seq*mask ====================
__global__ void k3c_select(const int* __restrict__ mask_, const float* __restrict__ w_2) {
    __shared__ float beta[LL];
    __shared__ float sw2[DD];
    __shared__ int smask[LL];
    int b = blockIdx.x, tid = threadIdx.x;
    if (tid < DD) sw2[tid] = w_2[tid];
    if (tid < LL) smask[tid] = mask_[b*LL + tid];
    __syncthreads();
    int wid = tid >> 5, lane = tid & 31;
    for (int l = wid; l < LL; l += 8) {
        float s = 0.f;
        const float* g = &g_gate[((size_t)b*LL + l)*DD];
        for (int d = lane; d < DD; d += 32) s += g[d] * sw2[d];
#pragma unroll
        for (int o = 16; o > 0; o >>= 1) s += __shfl_xor_sync(0xffffffffu, s, o);
        if (lane == 0) beta[l] = s;
    }
    __syncthreads();
    if (tid < DD) {
        float s = 0.f;
        for (int l = 0; l < LL; l++) {
            s += beta[l] * (float)smask[l] * g_seq[((size_t)b*LL + l)*DD + tid];
        }
        g_select[(size_t)b*DD + tid] = s;
    }
}

// ==================== K4: scores = select @ emb[1:].T ====================
__global__ void k4_scores(const float* __restrict__ emb, float* __restrict__ out) {
    __shared__ float Asm[KT*AST];
    __shared__ float Bsm[KT*BST];
    int tid = threadIdx.x;
    int m0 = blockIdx.y * TM;
    int n0 = blockIdx.x * 128;
    int tc = tid & 15, tr = tid >> 4;
    float acc[4][8] = {};
    for (int kt = 0; kt < 8; kt++) {
        int k0 = kt * KT;
#pragma unroll
        for (int t = 0; t < 4; t++) {
            int idx = tid + t*256;
            int kk = idx & 15, r = idx >> 4;
            Asm[kk*AST + r] = g_select[(size_t)(m0 + r)*DD + k0 + kk];
        }
#pragma unroll
        for (int t = 0; t < 8; t++) {
            int idx = tid + t*256;
            int kk = idx & 15, c = idx >> 4;
            int v = n0 + c;
            Bsm[kk*BST + c] = (v < NV) ? emb[(size_t)(v + 1)*DD + k0 + kk] : 0.f;
        }
        __syncthreads();
        mm_step(Asm, Bsm, acc, tr, tc);
        __syncthreads();
    }
#pragma unroll
    for (int i = 0; i < 4; i++) {
        int row = m0 + tr*4 + i;
#pragma unroll
        for (int j = 0; j < 8; j++) {
            int c = n0 + tc*8 + j;
            if (c < NV) out[(size_t)row*NV + c] = acc[i][j];
        }
    }
}

// ==================== host launcher ====================
extern "C" void kernel_launch(void* const* d_in, const int* in_sizes, int n_in,
                              void* d_out, int out_size) {
    const int*   items   = (const int*)  d_in[0];
    const int*   adj     = (const int*)  d_in[1];
    const int*   alias_  = (const int*)  d_in[2];
    const int*   mask_   = (const int*)  d_in[3];
    const float* emb     = (const float*)d_in[4];
    const float* img_emb = (const float*)d_in[5];
    const float* txt_emb = (const float*)d_in[6];
    const float* W_img   = (const float*)d_in[7];
    const float* b_img   = (const float*)d_in[8];
    const float* W_txt   = (const float*)d_in[9];
    const float* b_txt   = (const float*)d_in[10];
    const float* W_fuse  = (const float*)d_in[11];
    const float* b_fuse  = (const float*)d_in[12];
    const float* a_rel   = (const float*)d_in[13];
    const float* pos_emb = (const float*)d_in[14];
    const float* w_1     = (const float*)d_in[15];
    const float* w_2     = (const float*)d_in[16];
    const float* glu1_w  = (const float*)d_in[17];
    const float* glu1_b  = (const float*)d_in[18];
    const float* glu2_w  = (const float*)d_in[19];
    float* out = (float*)d_out;

    k0_combine<<<DD, DD>>>(W_img, W_txt, W_fuse, b_img, b_txt, b_fuse);
    k1_fuse<<<(BB*NN)/TM, 256>>>(items, emb, img_emb, txt_emb, W_fuse);
    k2_attn<<<BB, 256>>>(adj, alias_, mask_, a_rel);
    k3_hsg<<<BB, DD>>>(glu2_w, glu1_b);
    k3a_nh<<<(BB*LL)/TM, 256>>>(pos_emb, w_1);
    k3b_gate<<<(BB*LL)/TM, 256>>>(glu1_w);
    k3c_select<<<BB, 256>>>(mask_, w_2);
    dim3 g4((NV + 127)/128, BB/TM);
    k4_scores<<<g4, 256>>>(emb, out);
}

// round 5
// speedup vs baseline: 1.4603x; 1.4603x over previous
#include <cuda_runtime.h>
#include <cuda_bf16.h>
#include <cstdint>
#include <math.h>

typedef unsigned char      u8;
typedef unsigned short     u16;
typedef unsigned int       u32;
typedef unsigned long long u64;

// Problem sizes (fixed by reference)
#define BB 1024
#define NN 24
#define LL 24
#define DD 128
#define VV 40000
#define NV 39999      // V-1 output columns
#define ALPHA 0.2f
#define NEGC (-9e15f)

// SIMT GEMM tiling (k1/k3a/k3b)
#define TM 64
#define KT 16
#define AST 68
#define BST 132

// K4 HMMA tiling
#define NB4 313              // ceil(39999/128)
#define NPAD (NB4*128)       // 40064
#define TROWS 128
#define TSTRIDE 272          // bytes per row (17 x 16B -> conflict-free ldmatrix)
#define TILE_BYTES (TROWS*TSTRIDE)      // 34816
#define TILE_U4 (TILE_BYTES/16)         // 2176
#define TILE_U32 (TILE_BYTES/4)         // 8704
#define SMEM_K4 (4*TILE_BYTES)          // 139264

// -------- device scratch (no runtime allocations allowed) --------
__device__ float g_Wci[DD*DD];
__device__ float g_Wct[DD*DD];
__device__ float g_bcomb[DD];
__device__ float g_h[BB*NN*DD];
__device__ float g_seq[BB*LL*DD];
__device__ float g_nh[BB*LL*DD];
__device__ float g_gate[BB*LL*DD];
__device__ float g_hs[BB*DD];
__device__ float g_hsg[BB*DD];
__device__ float g_select[BB*DD];
// pre-swizzle-free padded bf16 hi/lo tiles for K4 HMMA GEMM
__device__ uint4 g_Bhi4[(size_t)NB4*TILE_U4];
__device__ uint4 g_Blo4[(size_t)NB4*TILE_U4];
__device__ uint4 g_Ahi4[8*TILE_U4];
__device__ uint4 g_Alo4[8*TILE_U4];

// ==================== helpers ====================
__device__ __forceinline__ u32 smem_u32(const void* p) {
    u32 a;
    asm("{ .reg .u64 t; cvta.to.shared.u64 t, %1; cvt.u32.u64 %0, t; }" : "=r"(a) : "l"(p));
    return a;
}
__device__ __forceinline__ void ldsm4(u32* r, u32 addr) {
    asm volatile("ldmatrix.sync.aligned.m8n8.x4.shared.b16 {%0,%1,%2,%3}, [%4];"
        : "=r"(r[0]), "=r"(r[1]), "=r"(r[2]), "=r"(r[3]) : "r"(addr));
}
__device__ __forceinline__ void mma16816(float* c, const u32* a, u32 b0, u32 b1) {
    asm volatile("mma.sync.aligned.m16n8k16.row.col.f32.bf16.bf16.f32 "
        "{%0,%1,%2,%3}, {%4,%5,%6,%7}, {%8,%9}, {%0,%1,%2,%3};"
        : "+f"(c[0]), "+f"(c[1]), "+f"(c[2]), "+f"(c[3])
        : "r"(a[0]), "r"(a[1]), "r"(a[2]), "r"(a[3]), "r"(b0), "r"(b1));
}
__device__ __forceinline__ void split_bf16(float v, u16& h, u16& l) {
    __nv_bfloat16 hb = __float2bfloat16(v);
    float rem = v - __bfloat162float(hb);
    __nv_bfloat16 lb = __float2bfloat16(rem);
    h = __bfloat16_as_ushort(hb);
    l = __bfloat16_as_ushort(lb);
}

// ==================== K0: fold W_img/W_txt into W_fuse ====================
__global__ void k0_combine(const float* __restrict__ W_img, const float* __restrict__ W_txt,
                           const float* __restrict__ W_fuse, const float* __restrict__ b_img,
                           const float* __restrict__ b_txt, const float* __restrict__ b_fuse) {
    int k = blockIdx.x, d = threadIdx.x;
    float s1 = 0.f, s2 = 0.f;
    for (int j = 0; j < DD; j++) {
        s1 += W_img[k*DD + j] * W_fuse[(DD   + j)*DD + d];
        s2 += W_txt[k*DD + j] * W_fuse[(2*DD + j)*DD + d];
    }
    g_Wci[k*DD + d] = s1;
    g_Wct[k*DD + d] = s2;
    if (k == 0) {
        float s = b_fuse[d];
        for (int j = 0; j < DD; j++)
            s += b_img[j]*W_fuse[(DD + j)*DD + d] + b_txt[j]*W_fuse[(2*DD + j)*DD + d];
        g_bcomb[d] = s;
    }
}

// ==================== SIMT GEMM micro-kernel ====================
__device__ __forceinline__ void mm_step(const float* Asm, const float* Bsm,
                                        float acc[4][8], int tr, int tc) {
#pragma unroll
    for (int kk = 0; kk < KT; kk++) {
        float4 a4 = *reinterpret_cast<const float4*>(&Asm[kk*AST + tr*4]);
        float4 b0 = *reinterpret_cast<const float4*>(&Bsm[kk*BST + tc*8]);
        float4 b1 = *reinterpret_cast<const float4*>(&Bsm[kk*BST + tc*8 + 4]);
        float av[4] = {a4.x, a4.y, a4.z, a4.w};
        float bv[8] = {b0.x, b0.y, b0.z, b0.w, b1.x, b1.y, b1.z, b1.w};
#pragma unroll
        for (int i = 0; i < 4; i++)
#pragma unroll
            for (int j = 0; j < 8; j++) acc[i][j] += av[i]*bv[j];
    }
}

// ==================== K1: fused multimodal embedding ====================
__global__ void k1_fuse(const int* __restrict__ items, const float* __restrict__ emb,
                        const float* __restrict__ img, const float* __restrict__ txt,
                        const float* __restrict__ W_fuse) {
    __shared__ float Asm[KT*AST];
    __shared__ float Bsm[KT*BST];
    __shared__ int sitem[TM];
    int tid = threadIdx.x;
    int m0 = blockIdx.x * TM;
    if (tid < TM) sitem[tid] = items[m0 + tid];
    int tc = tid & 15, tr = tid >> 4;
    float acc[4][8] = {};
    __syncthreads();
    for (int kt = 0; kt < 24; kt++) {
        int k0 = kt * KT;
        int seg = k0 >> 7;
        int kl  = k0 & 127;
        const float* src = (seg == 0) ? emb : ((seg == 1) ? img : txt);
        const float* Wp  = (seg == 0) ? W_fuse : ((seg == 1) ? g_Wci : g_Wct);
#pragma unroll
        for (int t = 0; t < 4; t++) {
            int idx = tid + t*256;
            int kk = idx & 15, r = idx >> 4;
            Asm[kk*AST + r] = src[(size_t)sitem[r]*DD + kl + kk];
        }
#pragma unroll
        for (int t = 0; t < 8; t++) {
            int idx = tid + t*256;
            int c = idx & 127, kk = idx >> 7;
            Bsm[kk*BST + c] = Wp[(kl + kk)*DD + c];
        }
        __syncthreads();
        mm_step(Asm, Bsm, acc, tr, tc);
        __syncthreads();
    }
#pragma unroll
    for (int i = 0; i < 4; i++) {
        int row = m0 + tr*4 + i;
#pragma unroll
        for (int j = 0; j < 8; j++) {
            int c = tc*8 + j;
            g_h[(size_t)row*DD + c] = acc[i][j] + g_bcomb[c];
        }
    }
}

// ==================== K2: RGAT attention + seq remap + masked mean ====================
__global__ void k2_attn(const int* __restrict__ adj, const int* __restrict__ alias_,
                        const int* __restrict__ mask_, const float* __restrict__ a_rel) {
    __shared__ float hsm[NN*DD];
    __shared__ float hag[NN*DD];
    __shared__ float logit[NN*NN];
    __shared__ float arel[4*DD];
    __shared__ int salias[LL];
    __shared__ int smask[LL];
    __shared__ float hpart[256];
    int b = blockIdx.x, tid = threadIdx.x;

    for (int idx = tid; idx < NN*DD; idx += 256) hsm[idx] = g_h[(size_t)b*NN*DD + idx];
    for (int idx = tid; idx < 4*DD;  idx += 256) arel[idx] = a_rel[idx];
    if (tid < LL) { salias[tid] = alias_[b*LL + tid]; smask[tid] = mask_[b*LL + tid]; }
    __syncthreads();

    int grp = tid >> 2, l4 = tid & 3;
    for (int p = grp; p < NN*NN; p += 64) {
        int i = p / NN, j = p % NN;
        int r = adj[(size_t)b*NN*NN + p];
        int rr = (r >= 1) ? (r - 1) : 0;
        const float* ar = &arel[rr*DD];
        const float* hi = &hsm[i*DD];
        const float* hj = &hsm[j*DD];
        float s = 0.f;
        int d0 = l4 * 32;
        for (int d = d0; d < d0 + 32; d++) s += hi[d]*hj[d]*ar[d];
        s += __shfl_xor_sync(0xffffffffu, s, 1, 4);
        s += __shfl_xor_sync(0xffffffffu, s, 2, 4);
        if (l4 == 0) {
            float e = (s > 0.f) ? s : ALPHA * s;
            logit[p] = (r == 0) ? NEGC : e;
        }
    }
    __syncthreads();

    if (tid < NN) {
        float m = -INFINITY;
        for (int j = 0; j < NN; j++) m = fmaxf(m, logit[tid*NN + j]);
        float ex[NN]; float ssum = 0.f;
        for (int j = 0; j < NN; j++) { ex[j] = expf(logit[tid*NN + j] - m); ssum += ex[j]; }
        float inv = 1.f / ssum;
        for (int j = 0; j < NN; j++) logit[tid*NN + j] = ex[j] * inv;
    }
    __syncthreads();

    for (int idx = tid; idx < NN*DD; idx += 256) {
        int i = idx >> 7, d = idx & 127;
        float s = 0.f;
        for (int j = 0; j < NN; j++) s += logit[i*NN + j] * hsm[j*DD + d];
        hag[idx] = s;
    }
    __syncthreads();

    float part = 0.f;
    for (int idx = tid; idx < LL*DD; idx += 256) {
        int l = idx >> 7;
        int d = idx & 127;
        float v = hag[salias[l]*DD + d];
        g_seq[(size_t)b*LL*DD + idx] = v;
        part += v * (float)smask[l];
    }
    hpart[tid] = part;
    __syncthreads();
    if (tid < DD) {
        int ms = 0;
        for (int l = 0; l < LL; l++) ms += smask[l];
        float denom = fmaxf((float)ms, 1.f);
        g_hs[(size_t)b*DD + tid] = (hpart[tid] + hpart[tid + 128]) / denom;
    }
}

// ==================== K3h: hsg = glu1_b + hs @ glu2_w ====================
__global__ void k3_hsg(const float* __restrict__ glu2_w, const float* __restrict__ glu1_b) {
    __shared__ float shs[DD];
    int b = blockIdx.x, d = threadIdx.x;
    shs[d] = g_hs[(size_t)b*DD + d];
    __syncthreads();
    float s = glu1_b[d];
    for (int k = 0; k < DD; k++) s += shs[k] * glu2_w[k*DD + d];
    g_hsg[(size_t)b*DD + d] = s;
}

// ==================== K3a: nh = tanh([pos_rev | seq] @ w_1) ====================
__global__ void k3a_nh(const float* __restrict__ pos_emb, const float* __restrict__ w_1) {
    __shared__ float Asm[KT*AST];
    __shared__ float Bsm[KT*BST];
    int tid = threadIdx.x;
    int m0 = blockIdx.x * TM;
    int tc = tid & 15, tr = tid >> 4;
    float acc[4][8] = {};
    for (int kt = 0; kt < 16; kt++) {
        int k0 = kt * KT;
#pragma unroll
        for (int t = 0; t < 4; t++) {
            int idx = tid + t*256;
            int kk = idx & 15, r = idx >> 4;
            int row = m0 + r;
            float a;
            if (k0 < DD) {
                int l = row % LL;
                a = pos_emb[(LL - 1 - l)*DD + k0 + kk];
            } else {
                a = g_seq[(size_t)row*DD + (k0 - DD) + kk];
            }
            Asm[kk*AST + r] = a;
        }
#pragma unroll
        for (int t = 0; t < 8; t++) {
            int idx = tid + t*256;
            int c = idx & 127, kk = idx >> 7;
            Bsm[kk*BST + c] = w_1[(k0 + kk)*DD + c];
        }
        __syncthreads();
        mm_step(Asm, Bsm, acc, tr, tc);
        __syncthreads();
    }
#pragma unroll
    for (int i = 0; i < 4; i++) {
        int row = m0 + tr*4 + i;
#pragma unroll
        for (int j = 0; j < 8; j++) {
            int c = tc*8 + j;
            g_nh[(size_t)row*DD + c] = tanhf(acc[i][j]);
        }
    }
}

// ==================== K3b: gate = sigmoid(nh @ glu1_w + hsg[b]) ====================
__global__ void k3b_gate(const float* __restrict__ glu1_w) {
    __shared__ float Asm[KT*AST];
    __shared__ float Bsm[KT*BST];
    int tid = threadIdx.x;
    int m0 = blockIdx.x * TM;
    int tc = tid & 15, tr = tid >> 4;
    float acc[4][8] = {};
    for (int kt = 0; kt < 8; kt++) {
        int k0 = kt * KT;
#pragma unroll
        for (int t = 0; t < 4; t++) {
            int idx = tid + t*256;
            int kk = idx & 15, r = idx >> 4;
            Asm[kk*AST + r] = g_nh[(size_t)(m0 + r)*DD + k0 + kk];
        }
#pragma unroll
        for (int t = 0; t < 8; t++) {
            int idx = tid + t*256;
            int c = idx & 127, kk = idx >> 7;
            Bsm[kk*BST + c] = glu1_w[(k0 + kk)*DD + c];
        }
        __syncthreads();
        mm_step(Asm, Bsm, acc, tr, tc);
        __syncthreads();
    }
#pragma unroll
    for (int i = 0; i < 4; i++) {
        int row = m0 + tr*4 + i;
        int b = row / LL;
#pragma unroll
        for (int j = 0; j < 8; j++) {
            int c = tc*8 + j;
            float v = acc[i][j] + g_hsg[(size_t)b*DD + c];
            g_gate[(size_t)row*DD + c] = 1.f / (1.f + expf(-v));
        }
    }
}

// ==================== K3c: beta = gate@w_2 ; select = sum_l beta*seq*mask ====================
__global__ void k3c_select(const int* __restrict__ mask_, const float* __restrict__ w_2) {
    __shared__ float beta[LL];
    __shared__ float sw2[DD];
    __shared__ int smask[LL];
    int b = blockIdx.x, tid = threadIdx.x;
    if (tid < DD) sw2[tid] = w_2[tid];
    if (tid < LL) smask[tid] = mask_[b*LL + tid];
    __syncthreads();
    int wid = tid >> 5, lane = tid & 31;
    for (int l = wid; l < LL; l += 8) {
        float s = 0.f;
        const float* g = &g_gate[((size_t)b*LL + l)*DD];
        for (int d = lane; d < DD; d += 32) s += g[d] * sw2[d];
#pragma unroll
        for (int o = 16; o > 0; o >>= 1) s += __shfl_xor_sync(0xffffffffu, s, o);
        if (lane == 0) beta[l] = s;
    }
    __syncthreads();
    if (tid < DD) {
        float s = 0.f;
        for (int l = 0; l < LL; l++)
            s += beta[l] * (float)smask[l] * g_seq[((size_t)b*LL + l)*DD + tid];
        g_select[(size_t)b*DD + tid] = s;
    }
}

// ==================== prep: emb -> padded bf16 hi/lo tiles (K-contiguous) ====================
__global__ void k_prep_B(const float* __restrict__ emb) {
    int idx = blockIdx.x * 256 + threadIdx.x;   // NPAD*64 pair-slots
    if (idx >= NPAD * 64) return;
    int r = idx >> 6;          // padded output-col index n
    int c2 = idx & 63;
    int c = c2 * 2;
    float v0 = 0.f, v1 = 0.f;
    if (r < NV) {
        const float* p = emb + (size_t)(r + 1) * DD + c;
        v0 = p[0]; v1 = p[1];
    }
    u16 h0, l0, h1, l1;
    split_bf16(v0, h0, l0);
    split_bf16(v1, h1, l1);
    u32 hi = (u32)h0 | ((u32)h1 << 16);
    u32 lo = (u32)l0 | ((u32)l1 << 16);
    size_t w = (size_t)(r >> 7) * TILE_U32 + (size_t)(r & 127) * (TSTRIDE/4) + c2;
    reinterpret_cast<u32*>(g_Bhi4)[w] = hi;
    reinterpret_cast<u32*>(g_Blo4)[w] = lo;
}

// ==================== prep: select -> padded bf16 hi/lo tiles ====================
__global__ void k_prep_A() {
    int idx = blockIdx.x * 256 + threadIdx.x;   // 1024*64 pair-slots
    int row = idx >> 6;
    int c2 = idx & 63;
    int c = c2 * 2;
    float v0 = g_select[(size_t)row * DD + c];
    float v1 = g_select[(size_t)row * DD + c + 1];
    u16 h0, l0, h1, l1;
    split_bf16(v0, h0, l0);
    split_bf16(v1, h1, l1);
    u32 hi = (u32)h0 | ((u32)h1 << 16);
    u32 lo = (u32)l0 | ((u32)l1 << 16);
    size_t w = (size_t)(row >> 7) * TILE_U32 + (size_t)(row & 127) * (TSTRIDE/4) + c2;
    reinterpret_cast<u32*>(g_Ahi4)[w] = hi;
    reinterpret_cast<u32*>(g_Alo4)[w] = lo;
}

// ==================== K4: scores GEMM with HMMA (split-bf16, 3 terms) ====================
// 256 threads; warp grid 2(m) x 4(n); each warp 64x32 out via m16n8k16.
__global__ void __launch_bounds__(256, 1) k4_mma(float* __restrict__ out) {
    extern __shared__ u8 dsm[];
    int tid = threadIdx.x;
    int wid = tid >> 5;
    int lane = tid & 31;
    int nb = blockIdx.x;   // output-col block (128 cols)
    int mb = blockIdx.y;   // row block (128 rows)

    // ---- linear copy of 4 tiles into smem ----
    {
        const uint4* srcs[4] = {
            g_Ahi4 + (size_t)mb * TILE_U4,
            g_Alo4 + (size_t)mb * TILE_U4,
            g_Bhi4 + (size_t)nb * TILE_U4,
            g_Blo4 + (size_t)nb * TILE_U4
        };
        uint4* dsm4 = reinterpret_cast<uint4*>(dsm);
#pragma unroll
        for (int t = 0; t < 4; t++) {
            const uint4* src = srcs[t];
            uint4* dst = dsm4 + t * TILE_U4;
            for (int i = tid; i < TILE_U4; i += 256)
                dst[i] = src[i];
        }
    }
    __syncthreads();

    u32 sbase = smem_u32(dsm);
    u32 sAhi = sbase;
    u32 sAlo = sbase + TILE_BYTES;
    u32 sBhi = sbase + 2*TILE_BYTES;
    u32 sBlo = sbase + 3*TILE_BYTES;

    int mwarp = wid >> 2;        // 0..1
    int nwarp = wid & 3;         // 0..3

    // ldmatrix per-lane offsets
    u32 aoff = (u32)(mwarp*64 + (lane & 15)) * TSTRIDE + ((lane >> 4) << 3) * 2;
    u32 boff = (u32)(nwarp*32 + (lane & 7) + ((lane >> 4) << 3)) * TSTRIDE
             + (((lane >> 3) & 1) << 3) * 2;

    float acc[4][4][4];
#pragma unroll
    for (int mi = 0; mi < 4; mi++)
#pragma unroll
        for (int ni = 0; ni < 4; ni++)
#pragma unroll
            for (int q = 0; q < 4; q++) acc[mi][ni][q] = 0.f;

#pragma unroll
    for (int ks = 0; ks < 8; ks++) {
        u32 kbyte = (u32)ks * 32;   // 16 bf16 = 32B per k-step
        u32 ahi[4][4], alo[4][4], bhi[2][4], blo[2][4];
#pragma unroll
        for (int mi = 0; mi < 4; mi++) {
            u32 off = aoff + (u32)(mi*16)*TSTRIDE + kbyte;
            ldsm4(ahi[mi], sAhi + off);
            ldsm4(alo[mi], sAlo + off);
        }
#pragma unroll
        for (int np = 0; np < 2; np++) {
            u32 off = boff + (u32)(np*16)*TSTRIDE + kbyte;
            ldsm4(bhi[np], sBhi + off);
            ldsm4(blo[np], sBlo + off);
        }
#pragma unroll
        for (int mi = 0; mi < 4; mi++) {
#pragma unroll
            for (int ni = 0; ni < 4; ni++) {
                int np = ni >> 1;
                int s = (ni & 1) * 2;
                mma16816(acc[mi][ni], ahi[mi], bhi[np][s], bhi[np][s+1]);
                mma16816(acc[mi][ni], ahi[mi], blo[np][s], blo[np][s+1]);
                mma16816(acc[mi][ni], alo[mi], bhi[np][s], bhi[np][s+1]);
            }
        }
    }
    __syncthreads();   // done with A/B tiles; reuse smem for C staging

    // ---- stage C in smem (128 x 128, stride 132 floats) ----
    float* Csm = reinterpret_cast<float*>(dsm);
    {
        int grp = lane >> 2, qid = lane & 3;
#pragma unroll
        for (int mi = 0; mi < 4; mi++) {
#pragma unroll
            for (int ni = 0; ni < 4; ni++) {
                int r0 = mwarp*64 + mi*16 + grp;
                int c0 = nwarp*32 + ni*8 + qid*2;
                Csm[r0*132 + c0]       = acc[mi][ni][0];
                Csm[r0*132 + c0 + 1]   = acc[mi][ni][1];
                Csm[(r0+8)*132 + c0]   = acc[mi][ni][2];
                Csm[(r0+8)*132 + c0+1] = acc[mi][ni][3];
            }
        }
    }
    __syncthreads();

    // ---- coalesced write to global ----
    {
        int n0 = nb * 128;
        size_t rbase = (size_t)mb * 128;
        for (int i = tid; i < 128*128; i += 256) {
            int r = i >> 7, c = i & 127;
            int gc = n0 + c;
            if (gc < NV)
                out[(rbase + r) * NV + gc] = Csm[r*132 + c];
        }
    }
}

// ==================== host launcher ====================
extern "C" void kernel_launch(void* const* d_in, const int* in_sizes, int n_in,
                              void* d_out, int out_size) {
    const int*   items   = (const int*)  d_in[0];
    const int*   adj     = (const int*)  d_in[1];
    const int*   alias_  = (const int*)  d_in[2];
    const int*   mask_   = (const int*)  d_in[3];
    const float* emb     = (const float*)d_in[4];
    const float* img_emb = (const float*)d_in[5];
    const float* txt_emb = (const float*)d_in[6];
    const float* W_img   = (const float*)d_in[7];
    const float* b_img   = (const float*)d_in[8];
    const float* W_txt   = (const float*)d_in[9];
    const float* b_txt   = (const float*)d_in[10];
    const float* W_fuse  = (const float*)d_in[11];
    const float* b_fuse  = (const float*)d_in[12];
    const float* a_rel   = (const float*)d_in[13];
    const float* pos_emb = (const float*)d_in[14];
    const float* w_1     = (const float*)d_in[15];
    const float* w_2     = (const float*)d_in[16];
    const float* glu1_w  = (const float*)d_in[17];
    const float* glu1_b  = (const float*)d_in[18];
    const float* glu2_w  = (const float*)d_in[19];
    float* out = (float*)d_out;

    cudaFuncSetAttribute(k4_mma, cudaFuncAttributeMaxDynamicSharedMemorySize, SMEM_K4);

    k_prep_B<<<(NPAD*64 + 255)/256, 256>>>(emb);
    k0_combine<<<DD, DD>>>(W_img, W_txt, W_fuse, b_img, b_txt, b_fuse);
    k1_fuse<<<(BB*NN)/TM, 256>>>(items, emb, img_emb, txt_emb, W_fuse);
    k2_attn<<<BB, 256>>>(adj, alias_, mask_, a_rel);
    k3_hsg<<<BB, DD>>>(glu2_w, glu1_b);
    k3a_nh<<<(BB*LL)/TM, 256>>>(pos_emb, w_1);
    k3b_gate<<<(BB*LL)/TM, 256>>>(glu1_w);
    k3c_select<<<BB, 256>>>(mask_, w_2);
    k_prep_A<<<(BB*64)/256, 256>>>();
    dim3 g4(NB4, BB/128);
    k4_mma<<<g4, 256, SMEM_K4>>>(out);
}

// round 6
// speedup vs baseline: 1.5494x; 1.0610x over previous
#include <cuda_runtime.h>
#include <cuda_bf16.h>
#include <cstdint>
#include <math.h>

typedef unsigned char      u8;
typedef unsigned short     u16;
typedef unsigned int       u32;
typedef unsigned long long u64;

// Problem sizes (fixed by reference)
#define BB 1024
#define NN 24
#define LL 24
#define DD 128
#define VV 40000
#define NV 39999      // V-1 output columns
#define ALPHA 0.2f
#define NEGC (-9e15f)

// SIMT GEMM tiling (k1/k3a/k3b)
#define TM 64
#define KT 16
#define AST 68
#define BST 132

// K4 HMMA tiling
#define NB4 313              // ceil(39999/128)
#define NPAD (NB4*128)       // 40064
#define TROWS 128
#define TSTRIDE 272          // bytes per row (17 x 16B -> conflict-free ldmatrix)
#define TILE_BYTES (TROWS*TSTRIDE)      // 34816
#define TILE_U4 (TILE_BYTES/16)         // 2176
#define TILE_U32 (TILE_BYTES/4)         // 8704
#define SMEM_K4 (4*TILE_BYTES)          // 139264

// -------- device scratch (no runtime allocations allowed) --------
__device__ float g_Wci[DD*DD];
__device__ float g_Wct[DD*DD];
__device__ float g_bcomb[DD];
__device__ float g_h[BB*NN*DD];
__device__ float g_seq[BB*LL*DD];
__device__ float g_nh[BB*LL*DD];
__device__ float g_gate[BB*LL*DD];
__device__ float g_hs[BB*DD];
__device__ float g_hsg[BB*DD];
__device__ float g_select[BB*DD];
// padded bf16 hi/lo tiles for K4 HMMA GEMM
__device__ uint4 g_Bhi4[(size_t)NB4*TILE_U4];
__device__ uint4 g_Blo4[(size_t)NB4*TILE_U4];
__device__ uint4 g_Ahi4[8*TILE_U4];
__device__ uint4 g_Alo4[8*TILE_U4];

// ==================== helpers ====================
__device__ __forceinline__ u32 smem_u32(const void* p) {
    u32 a;
    asm("{ .reg .u64 t; cvta.to.shared.u64 t, %1; cvt.u32.u64 %0, t; }" : "=r"(a) : "l"(p));
    return a;
}
__device__ __forceinline__ void ldsm4(u32* r, u32 addr) {
    asm volatile("ldmatrix.sync.aligned.m8n8.x4.shared.b16 {%0,%1,%2,%3}, [%4];"
        : "=r"(r[0]), "=r"(r[1]), "=r"(r[2]), "=r"(r[3]) : "r"(addr));
}
__device__ __forceinline__ void mma16816(float* c, const u32* a, u32 b0, u32 b1) {
    asm volatile("mma.sync.aligned.m16n8k16.row.col.f32.bf16.bf16.f32 "
        "{%0,%1,%2,%3}, {%4,%5,%6,%7}, {%8,%9}, {%0,%1,%2,%3};"
        : "+f"(c[0]), "+f"(c[1]), "+f"(c[2]), "+f"(c[3])
        : "r"(a[0]), "r"(a[1]), "r"(a[2]), "r"(a[3]), "r"(b0), "r"(b1));
}
__device__ __forceinline__ void split_bf16(float v, u16& h, u16& l) {
    __nv_bfloat16 hb = __float2bfloat16(v);
    float rem = v - __bfloat162float(hb);
    __nv_bfloat16 lb = __float2bfloat16(rem);
    h = __bfloat16_as_ushort(hb);
    l = __bfloat16_as_ushort(lb);
}

// ==================== K0: fold W_img/W_txt into W_fuse ====================
__global__ void k0_combine(const float* __restrict__ W_img, const float* __restrict__ W_txt,
                           const float* __restrict__ W_fuse, const float* __restrict__ b_img,
                           const float* __restrict__ b_txt, const float* __restrict__ b_fuse) {
    int k = blockIdx.x, d = threadIdx.x;
    float s1 = 0.f, s2 = 0.f;
    for (int j = 0; j < DD; j++) {
        s1 += W_img[k*DD + j] * W_fuse[(DD   + j)*DD + d];
        s2 += W_txt[k*DD + j] * W_fuse[(2*DD + j)*DD + d];
    }
    g_Wci[k*DD + d] = s1;
    g_Wct[k*DD + d] = s2;
    if (k == 0) {
        float s = b_fuse[d];
        for (int j = 0; j < DD; j++)
            s += b_img[j]*W_fuse[(DD + j)*DD + d] + b_txt[j]*W_fuse[(2*DD + j)*DD + d];
        g_bcomb[d] = s;
    }
}

// ==================== SIMT GEMM micro-kernel ====================
__device__ __forceinline__ void mm_step(const float* Asm, const float* Bsm,
                                        float acc[4][8], int tr, int tc) {
#pragma unroll
    for (int kk = 0; kk < KT; kk++) {
        float4 a4 = *reinterpret_cast<const float4*>(&Asm[kk*AST + tr*4]);
        float4 b0 = *reinterpret_cast<const float4*>(&Bsm[kk*BST + tc*8]);
        float4 b1 = *reinterpret_cast<const float4*>(&Bsm[kk*BST + tc*8 + 4]);
        float av[4] = {a4.x, a4.y, a4.z, a4.w};
        float bv[8] = {b0.x, b0.y, b0.z, b0.w, b1.x, b1.y, b1.z, b1.w};
#pragma unroll
        for (int i = 0; i < 4; i++)
#pragma unroll
            for (int j = 0; j < 8; j++) acc[i][j] += av[i]*bv[j];
    }
}

// ==================== K1: fused multimodal embedding ====================
__global__ void k1_fuse(const int* __restrict__ items, const float* __restrict__ emb,
                        const float* __restrict__ img, const float* __restrict__ txt,
                        const float* __restrict__ W_fuse) {
    __shared__ float Asm[KT*AST];
    __shared__ float Bsm[KT*BST];
    __shared__ int sitem[TM];
    int tid = threadIdx.x;
    int m0 = blockIdx.x * TM;
    if (tid < TM) sitem[tid] = items[m0 + tid];
    int tc = tid & 15, tr = tid >> 4;
    float acc[4][8] = {};
    __syncthreads();
    for (int kt = 0; kt < 24; kt++) {
        int k0 = kt * KT;
        int seg = k0 >> 7;
        int kl  = k0 & 127;
        const float* src = (seg == 0) ? emb : ((seg == 1) ? img : txt);
        const float* Wp  = (seg == 0) ? W_fuse : ((seg == 1) ? g_Wci : g_Wct);
#pragma unroll
        for (int t = 0; t < 4; t++) {
            int idx = tid + t*256;
            int kk = idx & 15, r = idx >> 4;
            Asm[kk*AST + r] = src[(size_t)sitem[r]*DD + kl + kk];
        }
#pragma unroll
        for (int t = 0; t < 8; t++) {
            int idx = tid + t*256;
            int c = idx & 127, kk = idx >> 7;
            Bsm[kk*BST + c] = Wp[(kl + kk)*DD + c];
        }
        __syncthreads();
        mm_step(Asm, Bsm, acc, tr, tc);
        __syncthreads();
    }
#pragma unroll
    for (int i = 0; i < 4; i++) {
        int row = m0 + tr*4 + i;
#pragma unroll
        for (int j = 0; j < 8; j++) {
            int c = tc*8 + j;
            g_h[(size_t)row*DD + c] = acc[i][j] + g_bcomb[c];
        }
    }
}

// ==================== K2: RGAT attention (vectorized) ====================
__global__ void __launch_bounds__(256) k2_attn(const int* __restrict__ adj,
                        const int* __restrict__ alias_,
                        const int* __restrict__ mask_, const float* __restrict__ a_rel) {
    __shared__ float hsm[NN*DD];
    __shared__ float hag[NN*DD];
    __shared__ float logit[NN*NN];
    __shared__ float arel[4*DD];
    __shared__ int salias[LL];
    __shared__ int smask[LL];
    __shared__ float4 hpart4[256];
    __shared__ float sdenom;
    int b = blockIdx.x, tid = threadIdx.x;

    // vectorized loads of h (24x128) and a_rel (4x128)
    {
        const float4* src = reinterpret_cast<const float4*>(&g_h[(size_t)b*NN*DD]);
        float4* dst = reinterpret_cast<float4*>(hsm);
        for (int i = tid; i < NN*DD/4; i += 256) dst[i] = src[i];
        const float4* asrc = reinterpret_cast<const float4*>(a_rel);
        float4* adst = reinterpret_cast<float4*>(arel);
        if (tid < 4*DD/4) adst[tid] = asrc[tid];
    }
    if (tid < LL) { salias[tid] = alias_[b*LL + tid]; smask[tid] = mask_[b*LL + tid]; }
    if (tid == 0) {
        // denom computed once (cheap; overlapped with other threads' loads)
        int ms = 0;
        for (int l = 0; l < LL; l++) ms += mask_[b*LL + l];
        sdenom = fmaxf((float)ms, 1.f);
    }
    __syncthreads();

    // ---- edge scores: 8 threads per pair, float4 math ----
    {
        int grp = tid >> 3, l8 = tid & 7;   // 32 pair-groups
        const float4* h4 = reinterpret_cast<const float4*>(hsm);
        const float4* a4 = reinterpret_cast<const float4*>(arel);
        for (int p = grp; p < NN*NN; p += 32) {
            int i = p / NN, j = p - i*NN;
            int r = adj[(size_t)b*NN*NN + p];
            int rr = (r >= 1) ? (r - 1) : 0;
            const float4* hi4 = h4 + i*32 + l8*4;
            const float4* hj4 = h4 + j*32 + l8*4;
            const float4* ar4 = a4 + rr*32 + l8*4;
            float s = 0.f;
#pragma unroll
            for (int q = 0; q < 4; q++) {
                float4 x = hi4[q], y = hj4[q], z = ar4[q];
                s += x.x*y.x*z.x + x.y*y.y*z.y + x.z*y.z*z.z + x.w*y.w*z.w;
            }
            s += __shfl_xor_sync(0xffffffffu, s, 1, 8);
            s += __shfl_xor_sync(0xffffffffu, s, 2, 8);
            s += __shfl_xor_sync(0xffffffffu, s, 4, 8);
            if (l8 == 0) {
                float e = (s > 0.f) ? s : ALPHA * s;
                logit[p] = (r == 0) ? NEGC : e;
            }
        }
    }
    __syncthreads();

    // ---- row softmax (24 rows, 1 thread each; matches jax max-subtract) ----
    if (tid < NN) {
        float m = -INFINITY;
#pragma unroll
        for (int j = 0; j < NN; j++) m = fmaxf(m, logit[tid*NN + j]);
        float ex[NN]; float ssum = 0.f;
#pragma unroll
        for (int j = 0; j < NN; j++) { ex[j] = __expf(logit[tid*NN + j] - m); ssum += ex[j]; }
        float inv = 1.f / ssum;
#pragma unroll
        for (int j = 0; j < NN; j++) logit[tid*NN + j] = ex[j] * inv;
    }
    __syncthreads();

    // ---- aggregate: hag = att @ h, float4 ----
    {
        const float4* h4 = reinterpret_cast<const float4*>(hsm);
        float4* hag4 = reinterpret_cast<float4*>(hag);
        for (int idx = tid; idx < NN*32; idx += 256) {
            int i = idx >> 5;       // row
            int d4 = idx & 31;
            float4 s = make_float4(0.f, 0.f, 0.f, 0.f);
#pragma unroll
            for (int j = 0; j < NN; j++) {
                float w = logit[i*NN + j];
                float4 hv = h4[j*32 + d4];
                s.x += w*hv.x; s.y += w*hv.y; s.z += w*hv.z; s.w += w*hv.w;
            }
            hag4[idx] = s;
        }
    }
    __syncthreads();

    // ---- seq = hag[alias]; hs = masked mean (float4) ----
    {
        const float4* hag4 = reinterpret_cast<const float4*>(hag);
        float4* seq4 = reinterpret_cast<float4*>(&g_seq[(size_t)b*LL*DD]);
        float4 part = make_float4(0.f, 0.f, 0.f, 0.f);
        for (int idx = tid; idx < LL*32; idx += 256) {
            int l = idx >> 5;
            int d4 = idx & 31;      // constant per thread under +256 stride
            float4 v = hag4[salias[l]*32 + d4];
            seq4[idx] = v;
            float mf = (float)smask[l];
            part.x += v.x*mf; part.y += v.y*mf; part.z += v.z*mf; part.w += v.w*mf;
        }
        hpart4[tid] = part;
    }
    __syncthreads();
    if (tid < 32) {
        float4 s = make_float4(0.f, 0.f, 0.f, 0.f);
#pragma unroll
        for (int w = 0; w < 8; w++) {
            float4 v = hpart4[tid + 32*w];
            s.x += v.x; s.y += v.y; s.z += v.z; s.w += v.w;
        }
        float inv = 1.f / sdenom;
        s.x *= inv; s.y *= inv; s.z *= inv; s.w *= inv;
        reinterpret_cast<float4*>(&g_hs[(size_t)b*DD])[tid] = s;
    }
}

// ==================== K3h: hsg = glu1_b + hs @ glu2_w ====================
__global__ void k3_hsg(const float* __restrict__ glu2_w, const float* __restrict__ glu1_b) {
    __shared__ float shs[DD];
    int b = blockIdx.x, d = threadIdx.x;
    shs[d] = g_hs[(size_t)b*DD + d];
    __syncthreads();
    float s = glu1_b[d];
    for (int k = 0; k < DD; k++) s += shs[k] * glu2_w[k*DD + d];
    g_hsg[(size_t)b*DD + d] = s;
}

// ==================== K3a: nh = tanh([pos_rev | seq] @ w_1) ====================
__global__ void k3a_nh(const float* __restrict__ pos_emb, const float* __restrict__ w_1) {
    __shared__ float Asm[KT*AST];
    __shared__ float Bsm[KT*BST];
    int tid = threadIdx.x;
    int m0 = blockIdx.x * TM;
    int tc = tid & 15, tr = tid >> 4;
    float acc[4][8] = {};
    for (int kt = 0; kt < 16; kt++) {
        int k0 = kt * KT;
#pragma unroll
        for (int t = 0; t < 4; t++) {
            int idx = tid + t*256;
            int kk = idx & 15, r = idx >> 4;
            int row = m0 + r;
            float a;
            if (k0 < DD) {
                int l = row % LL;
                a = pos_emb[(LL - 1 - l)*DD + k0 + kk];
            } else {
                a = g_seq[(size_t)row*DD + (k0 - DD) + kk];
            }
            Asm[kk*AST + r] = a;
        }
#pragma unroll
        for (int t = 0; t < 8; t++) {
            int idx = tid + t*256;
            int c = idx & 127, kk = idx >> 7;
            Bsm[kk*BST + c] = w_1[(k0 + kk)*DD + c];
        }
        __syncthreads();
        mm_step(Asm, Bsm, acc, tr, tc);
        __syncthreads();
    }
#pragma unroll
    for (int i = 0; i < 4; i++) {
        int row = m0 + tr*4 + i;
#pragma unroll
        for (int j = 0; j < 8; j++) {
            int c = tc*8 + j;
            g_nh[(size_t)row*DD + c] = tanhf(acc[i][j]);
        }
    }
}

// ==================== K3b: gate = sigmoid(nh @ glu1_w + hsg[b]) ====================
__global__ void k3b_gate(const float* __restrict__ glu1_w) {
    __shared__ float Asm[KT*AST];
    __shared__ float Bsm[KT*BST];
    int tid = threadIdx.x;
    int m0 = blockIdx.x * TM;
    int tc = tid & 15, tr = tid >> 4;
    float acc[4][8] = {};
    for (int kt = 0; kt < 8; kt++) {
        int k0 = kt * KT;
#pragma unroll
        for (int t = 0; t < 4; t++) {
            int idx = tid + t*256;
            int kk = idx & 15, r = idx >> 4;
            Asm[kk*AST + r] = g_nh[(size_t)(m0 + r)*DD + k0 + kk];
        }
#pragma unroll
        for (int t = 0; t < 8; t++) {
            int idx = tid + t*256;
            int c = idx & 127, kk = idx >> 7;
            Bsm[kk*BST + c] = glu1_w[(k0 + kk)*DD + c];
        }
        __syncthreads();
        mm_step(Asm, Bsm, acc, tr, tc);
        __syncthreads();
    }
#pragma unroll
    for (int i = 0; i < 4; i++) {
        int row = m0 + tr*4 + i;
        int b = row / LL;
#pragma unroll
        for (int j = 0; j < 8; j++) {
            int c = tc*8 + j;
            float v = acc[i][j] + g_hsg[(size_t)b*DD + c];
            g_gate[(size_t)row*DD + c] = 1.f / (1.f + expf(-v));
        }
    }
}

// ==================== K3c: beta = gate@w_2 ; select = sum_l beta*seq*mask ====================
__global__ void k3c_select(const int* __restrict__ mask_, const float* __restrict__ w_2) {
    __shared__ float beta[LL];
    __shared__ float sw2[DD];
    __shared__ int smask[LL];
    int b = blockIdx.x, tid = threadIdx.x;
    if (tid < DD) sw2[tid] = w_2[tid];
    if (tid < LL) smask[tid] = mask_[b*LL + tid];
    __syncthreads();
    int wid = tid >> 5, lane = tid & 31;
    for (int l = wid; l < LL; l += 8) {
        float s = 0.f;
        const float* g = &g_gate[((size_t)b*LL + l)*DD];
        for (int d = lane; d < DD; d += 32) s += g[d] * sw2[d];
#pragma unroll
        for (int o = 16; o > 0; o >>= 1) s += __shfl_xor_sync(0xffffffffu, s, o);
        if (lane == 0) beta[l] = s;
    }
    __syncthreads();
    if (tid < DD) {
        float s = 0.f;
        for (int l = 0; l < LL; l++)
            s += beta[l] * (float)smask[l] * g_seq[((size_t)b*LL + l)*DD + tid];
        g_select[(size_t)b*DD + tid] = s;
    }
}

// ==================== prep: emb -> padded bf16 hi/lo tiles (K-contiguous) ====================
__global__ void k_prep_B(const float* __restrict__ emb) {
    int idx = blockIdx.x * 256 + threadIdx.x;   // NPAD*64 pair-slots
    if (idx >= NPAD * 64) return;
    int r = idx >> 6;          // padded output-col index n
    int c2 = idx & 63;
    int c = c2 * 2;
    float v0 = 0.f, v1 = 0.f;
    if (r < NV) {
        const float* p = emb + (size_t)(r + 1) * DD + c;
        v0 = p[0]; v1 = p[1];
    }
    u16 h0, l0, h1, l1;
    split_bf16(v0, h0, l0);
    split_bf16(v1, h1, l1);
    u32 hi = (u32)h0 | ((u32)h1 << 16);
    u32 lo = (u32)l0 | ((u32)l1 << 16);
    size_t w = (size_t)(r >> 7) * TILE_U32 + (size_t)(r & 127) * (TSTRIDE/4) + c2;
    reinterpret_cast<u32*>(g_Bhi4)[w] = hi;
    reinterpret_cast<u32*>(g_Blo4)[w] = lo;
}

// ==================== prep: select -> padded bf16 hi/lo tiles ====================
__global__ void k_prep_A() {
    int idx = blockIdx.x * 256 + threadIdx.x;   // 1024*64 pair-slots
    int row = idx >> 6;
    int c2 = idx & 63;
    int c = c2 * 2;
    float v0 = g_select[(size_t)row * DD + c];
    float v1 = g_select[(size_t)row * DD + c + 1];
    u16 h0, l0, h1, l1;
    split_bf16(v0, h0, l0);
    split_bf16(v1, h1, l1);
    u32 hi = (u32)h0 | ((u32)h1 << 16);
    u32 lo = (u32)l0 | ((u32)l1 << 16);
    size_t w = (size_t)(row >> 7) * TILE_U32 + (size_t)(row & 127) * (TSTRIDE/4) + c2;
    reinterpret_cast<u32*>(g_Ahi4)[w] = hi;
    reinterpret_cast<u32*>(g_Alo4)[w] = lo;
}

// ==================== K4: scores GEMM with HMMA (split-bf16, 3 terms) ====================
__global__ void __launch_bounds__(256, 1) k4_mma(float* __restrict__ out) {
    extern __shared__ u8 dsm[];
    int tid = threadIdx.x;
    int wid = tid >> 5;
    int lane = tid & 31;
    int nb = blockIdx.x;   // output-col block (128 cols)
    int mb = blockIdx.y;   // row block (128 rows)

    {
        const uint4* srcs[4] = {
            g_Ahi4 + (size_t)mb * TILE_U4,
            g_Alo4 + (size_t)mb * TILE_U4,
            g_Bhi4 + (size_t)nb * TILE_U4,
            g_Blo4 + (size_t)nb * TILE_U4
        };
        uint4* dsm4 = reinterpret_cast<uint4*>(dsm);
#pragma unroll
        for (int t = 0; t < 4; t++) {
            const uint4* src = srcs[t];
            uint4* dst = dsm4 + t * TILE_U4;
            for (int i = tid; i < TILE_U4; i += 256)
                dst[i] = src[i];
        }
    }
    __syncthreads();

    u32 sbase = smem_u32(dsm);
    u32 sAhi = sbase;
    u32 sAlo = sbase + TILE_BYTES;
    u32 sBhi = sbase + 2*TILE_BYTES;
    u32 sBlo = sbase + 3*TILE_BYTES;

    int mwarp = wid >> 2;        // 0..1
    int nwarp = wid & 3;         // 0..3

    u32 aoff = (u32)(mwarp*64 + (lane & 15)) * TSTRIDE + ((lane >> 4) << 3) * 2;
    u32 boff = (u32)(nwarp*32 + (lane & 7) + ((lane >> 4) << 3)) * TSTRIDE
             + (((lane >> 3) & 1) << 3) * 2;

    float acc[4][4][4];
#pragma unroll
    for (int mi = 0; mi < 4; mi++)
#pragma unroll
        for (int ni = 0; ni < 4; ni++)
#pragma unroll
            for (int q = 0; q < 4; q++) acc[mi][ni][q] = 0.f;

#pragma unroll
    for (int ks = 0; ks < 8; ks++) {
        u32 kbyte = (u32)ks * 32;
        u32 ahi[4][4], alo[4][4], bhi[2][4], blo[2][4];
#pragma unroll
        for (int mi = 0; mi < 4; mi++) {
            u32 off = aoff + (u32)(mi*16)*TSTRIDE + kbyte;
            ldsm4(ahi[mi], sAhi + off);
            ldsm4(alo[mi], sAlo + off);
        }
#pragma unroll
        for (int np = 0; np < 2; np++) {
            u32 off = boff + (u32)(np*16)*TSTRIDE + kbyte;
            ldsm4(bhi[np], sBhi + off);
            ldsm4(blo[np], sBlo + off);
        }
#pragma unroll
        for (int mi = 0; mi < 4; mi++) {
#pragma unroll
            for (int ni = 0; ni < 4; ni++) {
                int np = ni >> 1;
                int s = (ni & 1) * 2;
                mma16816(acc[mi][ni], ahi[mi], bhi[np][s], bhi[np][s+1]);
                mma16816(acc[mi][ni], ahi[mi], blo[np][s], blo[np][s+1]);
                mma16816(acc[mi][ni], alo[mi], bhi[np][s], bhi[np][s+1]);
            }
        }
    }
    __syncthreads();

    float* Csm = reinterpret_cast<float*>(dsm);
    {
        int grp = lane >> 2, qid = lane & 3;
#pragma unroll
        for (int mi = 0; mi < 4; mi++) {
#pragma unroll
            for (int ni = 0; ni < 4; ni++) {
                int r0 = mwarp*64 + mi*16 + grp;
                int c0 = nwarp*32 + ni*8 + qid*2;
                Csm[r0*132 + c0]       = acc[mi][ni][0];
                Csm[r0*132 + c0 + 1]   = acc[mi][ni][1];
                Csm[(r0+8)*132 + c0]   = acc[mi][ni][2];
                Csm[(r0+8)*132 + c0+1] = acc[mi][ni][3];
            }
        }
    }
    __syncthreads();

    {
        int n0 = nb * 128;
        size_t rbase = (size_t)mb * 128;
        for (int i = tid; i < 128*128; i += 256) {
            int r = i >> 7, c = i & 127;
            int gc = n0 + c;
            if (gc < NV)
                out[(rbase + r) * NV + gc] = Csm[r*132 + c];
        }
    }
}

// ==================== host launcher ====================
extern "C" void kernel_launch(void* const* d_in, const int* in_sizes, int n_in,
                              void* d_out, int out_size) {
    const int*   items   = (const int*)  d_in[0];
    const int*   adj     = (const int*)  d_in[1];
    const int*   alias_  = (const int*)  d_in[2];
    const int*   mask_   = (const int*)  d_in[3];
    const float* emb     = (const float*)d_in[4];
    const float* img_emb = (const float*)d_in[5];
    const float* txt_emb = (const float*)d_in[6];
    const float* W_img   = (const float*)d_in[7];
    const float* b_img   = (const float*)d_in[8];
    const float* W_txt   = (const float*)d_in[9];
    const float* b_txt   = (const float*)d_in[10];
    const float* W_fuse  = (const float*)d_in[11];
    const float* b_fuse  = (const float*)d_in[12];
    const float* a_rel   = (const float*)d_in[13];
    const float* pos_emb = (const float*)d_in[14];
    const float* w_1     = (const float*)d_in[15];
    const float* w_2     = (const float*)d_in[16];
    const float* glu1_w  = (const float*)d_in[17];
    const float* glu1_b  = (const float*)d_in[18];
    const float* glu2_w  = (const float*)d_in[19];
    float* out = (float*)d_out;

    cudaFuncSetAttribute(k4_mma, cudaFuncAttributeMaxDynamicSharedMemorySize, SMEM_K4);

    k_prep_B<<<(NPAD*64 + 255)/256, 256>>>(emb);
    k0_combine<<<DD, DD>>>(W_img, W_txt, W_fuse, b_img, b_txt, b_fuse);
    k1_fuse<<<(BB*NN)/TM, 256>>>(items, emb, img_emb, txt_emb, W_fuse);
    k2_attn<<<BB, 256>>>(adj, alias_, mask_, a_rel);
    k3_hsg<<<BB, DD>>>(glu2_w, glu1_b);
    k3a_nh<<<(BB*LL)/TM, 256>>>(pos_emb, w_1);
    k3b_gate<<<(BB*LL)/TM, 256>>>(glu1_w);
    k3c_select<<<BB, 256>>>(mask_, w_2);
    k_prep_A<<<(BB*64)/256, 256>>>();
    dim3 g4(NB4, BB/128);
    k4_mma<<<g4, 256, SMEM_K4>>>(out);
}

// round 7
// speedup vs baseline: 1.6460x; 1.0623x over previous
#include <cuda_runtime.h>
#include <cuda_bf16.h>
#include <cstdint>
#include <math.h>

typedef unsigned char      u8;
typedef unsigned short     u16;
typedef unsigned int       u32;
typedef unsigned long long u64;

// Problem sizes (fixed by reference)
#define BB 1024
#define NN 24
#define LL 24
#define DD 128
#define VV 40000
#define NV 39999      // V-1 output columns
#define ALPHA 0.2f
#define NEGC (-9e15f)

// SIMT GEMM tiling (k1/k3a/k3b)
#define TM 64
#define KT 16
#define AST 68
#define BST 132

// K4 HMMA tiling
#define NB4 313              // ceil(39999/128)
#define NPAD (NB4*128)       // 40064
#define TROWS 128
#define TSTRIDE 272          // bytes per row (17 x 16B -> conflict-free ldmatrix)
#define TILE_BYTES (TROWS*TSTRIDE)      // 34816
#define TILE_U4 (TILE_BYTES/16)         // 2176
#define TILE_U32 (TILE_BYTES/4)         // 8704
#define SMEM_K4 (4*TILE_BYTES)          // 139264

// -------- device scratch (no runtime allocations allowed) --------
__device__ float g_Wci[DD*DD];
__device__ float g_Wct[DD*DD];
__device__ float g_bcomb[DD];
__device__ float g_h[BB*NN*DD];
__device__ float g_seq[BB*LL*DD];
__device__ float g_nh[BB*LL*DD];
__device__ float g_gate[BB*LL*DD];
__device__ float g_hs[BB*DD];
__device__ float g_hsg[BB*DD];
__device__ float g_select[BB*DD];
// padded bf16 hi/lo tiles for K4 HMMA GEMM
__device__ uint4 g_Bhi4[(size_t)NB4*TILE_U4];
__device__ uint4 g_Blo4[(size_t)NB4*TILE_U4];
__device__ uint4 g_Ahi4[8*TILE_U4];
__device__ uint4 g_Alo4[8*TILE_U4];

// ==================== helpers ====================
__device__ __forceinline__ u32 smem_u32(const void* p) {
    u32 a;
    asm("{ .reg .u64 t; cvta.to.shared.u64 t, %1; cvt.u32.u64 %0, t; }" : "=r"(a) : "l"(p));
    return a;
}
__device__ __forceinline__ void ldsm4(u32* r, u32 addr) {
    asm volatile("ldmatrix.sync.aligned.m8n8.x4.shared.b16 {%0,%1,%2,%3}, [%4];"
        : "=r"(r[0]), "=r"(r[1]), "=r"(r[2]), "=r"(r[3]) : "r"(addr));
}
__device__ __forceinline__ void mma16816(float* c, const u32* a, u32 b0, u32 b1) {
    asm volatile("mma.sync.aligned.m16n8k16.row.col.f32.bf16.bf16.f32 "
        "{%0,%1,%2,%3}, {%4,%5,%6,%7}, {%8,%9}, {%0,%1,%2,%3};"
        : "+f"(c[0]), "+f"(c[1]), "+f"(c[2]), "+f"(c[3])
        : "r"(a[0]), "r"(a[1]), "r"(a[2]), "r"(a[3]), "r"(b0), "r"(b1));
}
__device__ __forceinline__ void split_bf16(float v, u16& h, u16& l) {
    __nv_bfloat16 hb = __float2bfloat16(v);
    float rem = v - __bfloat162float(hb);
    __nv_bfloat16 lb = __float2bfloat16(rem);
    h = __bfloat16_as_ushort(hb);
    l = __bfloat16_as_ushort(lb);
}

// ==================== K0: fold W_img/W_txt into W_fuse ====================
__global__ void k0_combine(const float* __restrict__ W_img, const float* __restrict__ W_txt,
                           const float* __restrict__ W_fuse, const float* __restrict__ b_img,
                           const float* __restrict__ b_txt, const float* __restrict__ b_fuse) {
    int k = blockIdx.x, d = threadIdx.x;
    float s1 = 0.f, s2 = 0.f;
    for (int j = 0; j < DD; j++) {
        s1 += W_img[k*DD + j] * W_fuse[(DD   + j)*DD + d];
        s2 += W_txt[k*DD + j] * W_fuse[(2*DD + j)*DD + d];
    }
    g_Wci[k*DD + d] = s1;
    g_Wct[k*DD + d] = s2;
    if (k == 0) {
        float s = b_fuse[d];
        for (int j = 0; j < DD; j++)
            s += b_img[j]*W_fuse[(DD + j)*DD + d] + b_txt[j]*W_fuse[(2*DD + j)*DD + d];
        g_bcomb[d] = s;
    }
}

// ==================== SIMT GEMM micro-kernel ====================
__device__ __forceinline__ void mm_step(const float* Asm, const float* Bsm,
                                        float acc[4][8], int tr, int tc) {
#pragma unroll
    for (int kk = 0; kk < KT; kk++) {
        float4 a4 = *reinterpret_cast<const float4*>(&Asm[kk*AST + tr*4]);
        float4 b0 = *reinterpret_cast<const float4*>(&Bsm[kk*BST + tc*8]);
        float4 b1 = *reinterpret_cast<const float4*>(&Bsm[kk*BST + tc*8 + 4]);
        float av[4] = {a4.x, a4.y, a4.z, a4.w};
        float bv[8] = {b0.x, b0.y, b0.z, b0.w, b1.x, b1.y, b1.z, b1.w};
#pragma unroll
        for (int i = 0; i < 4; i++)
#pragma unroll
            for (int j = 0; j < 8; j++) acc[i][j] += av[i]*bv[j];
    }
}

// ==================== K1: fused multimodal embedding ====================
__global__ void k1_fuse(const int* __restrict__ items, const float* __restrict__ emb,
                        const float* __restrict__ img, const float* __restrict__ txt,
                        const float* __restrict__ W_fuse) {
    __shared__ float Asm[KT*AST];
    __shared__ float Bsm[KT*BST];
    __shared__ int sitem[TM];
    int tid = threadIdx.x;
    int m0 = blockIdx.x * TM;
    if (tid < TM) sitem[tid] = items[m0 + tid];
    int tc = tid & 15, tr = tid >> 4;
    float acc[4][8] = {};
    __syncthreads();
    for (int kt = 0; kt < 24; kt++) {
        int k0 = kt * KT;
        int seg = k0 >> 7;
        int kl  = k0 & 127;
        const float* src = (seg == 0) ? emb : ((seg == 1) ? img : txt);
        const float* Wp  = (seg == 0) ? W_fuse : ((seg == 1) ? g_Wci : g_Wct);
#pragma unroll
        for (int t = 0; t < 4; t++) {
            int idx = tid + t*256;
            int kk = idx & 15, r = idx >> 4;
            Asm[kk*AST + r] = src[(size_t)sitem[r]*DD + kl + kk];
        }
#pragma unroll
        for (int t = 0; t < 8; t++) {
            int idx = tid + t*256;
            int c = idx & 127, kk = idx >> 7;
            Bsm[kk*BST + c] = Wp[(kl + kk)*DD + c];
        }
        __syncthreads();
        mm_step(Asm, Bsm, acc, tr, tc);
        __syncthreads();
    }
#pragma unroll
    for (int i = 0; i < 4; i++) {
        int row = m0 + tr*4 + i;
#pragma unroll
        for (int j = 0; j < 8; j++) {
            int c = tc*8 + j;
            g_h[(size_t)row*DD + c] = acc[i][j] + g_bcomb[c];
        }
    }
}

// ==================== K2: RGAT attention (warp-per-row, register w_r) ====================
__global__ void __launch_bounds__(256) k2_attn(const int* __restrict__ adj,
                        const int* __restrict__ alias_,
                        const int* __restrict__ mask_, const float* __restrict__ a_rel) {
    __shared__ float hsm[NN*DD];
    __shared__ float hag[NN*DD];
    __shared__ float logit[NN*NN];
    __shared__ int sadj[NN*NN];
    __shared__ int salias[LL];
    __shared__ int smask[LL];
    __shared__ float4 hpart4[256];
    __shared__ float sdenom;
    int b = blockIdx.x, tid = threadIdx.x;
    int wid = tid >> 5, lane = tid & 31;

    // a_rel rows kept in registers, lane-parallel float4 (same for all i)
    float4 areg[4];
    {
        const float4* a4 = reinterpret_cast<const float4*>(a_rel);
#pragma unroll
        for (int r = 0; r < 4; r++) areg[r] = a4[r*32 + lane];
    }
    // loads: h (float4), adj (coalesced), alias/mask
    {
        const float4* src = reinterpret_cast<const float4*>(&g_h[(size_t)b*NN*DD]);
        float4* dst = reinterpret_cast<float4*>(hsm);
        for (int i = tid; i < NN*DD/4; i += 256) dst[i] = src[i];
        const int* asrc = adj + (size_t)b*NN*NN;
        for (int i = tid; i < NN*NN; i += 256) sadj[i] = asrc[i];
    }
    if (tid < LL) { salias[tid] = alias_[b*LL + tid]; smask[tid] = mask_[b*LL + tid]; }
    if (tid == 0) {
        int ms = 0;
        for (int l = 0; l < LL; l++) ms += mask_[b*LL + l];
        sdenom = fmaxf((float)ms, 1.f);
    }
    __syncthreads();

    // ---- edge scores: warp per i-row; w_r = h[i] ⊙ a_r in registers ----
    {
        const float4* h4 = reinterpret_cast<const float4*>(hsm);
        for (int i = wid; i < NN; i += 8) {
            float4 hi = h4[i*32 + lane];
            float4 w0, w1, w2, w3;
            w0.x = hi.x*areg[0].x; w0.y = hi.y*areg[0].y; w0.z = hi.z*areg[0].z; w0.w = hi.w*areg[0].w;
            w1.x = hi.x*areg[1].x; w1.y = hi.y*areg[1].y; w1.z = hi.z*areg[1].z; w1.w = hi.w*areg[1].w;
            w2.x = hi.x*areg[2].x; w2.y = hi.y*areg[2].y; w2.z = hi.z*areg[2].z; w2.w = hi.w*areg[2].w;
            w3.x = hi.x*areg[3].x; w3.y = hi.y*areg[3].y; w3.z = hi.z*areg[3].z; w3.w = hi.w*areg[3].w;
#pragma unroll 4
            for (int j = 0; j < NN; j++) {
                float4 hj = h4[j*32 + lane];
                float s0 = w0.x*hj.x + w0.y*hj.y + w0.z*hj.z + w0.w*hj.w;
                float s1 = w1.x*hj.x + w1.y*hj.y + w1.z*hj.z + w1.w*hj.w;
                float s2 = w2.x*hj.x + w2.y*hj.y + w2.z*hj.z + w2.w*hj.w;
                float s3 = w3.x*hj.x + w3.y*hj.y + w3.z*hj.z + w3.w*hj.w;
#pragma unroll
                for (int o = 16; o > 0; o >>= 1) {
                    s0 += __shfl_xor_sync(0xffffffffu, s0, o);
                    s1 += __shfl_xor_sync(0xffffffffu, s1, o);
                    s2 += __shfl_xor_sync(0xffffffffu, s2, o);
                    s3 += __shfl_xor_sync(0xffffffffu, s3, o);
                }
                if (lane == 0) {
                    int r = sadj[i*NN + j];
                    float sv = (r == 1) ? s0 : (r == 2) ? s1 : (r == 3) ? s2 : s3;
                    float e = (sv > 0.f) ? sv : ALPHA * sv;
                    logit[i*NN + j] = (r == 0) ? NEGC : e;
                }
            }
        }
    }
    __syncthreads();

    // ---- row softmax (24 rows, 1 thread each; matches jax max-subtract) ----
    if (tid < NN) {
        float m = -INFINITY;
#pragma unroll
        for (int j = 0; j < NN; j++) m = fmaxf(m, logit[tid*NN + j]);
        float ex[NN]; float ssum = 0.f;
#pragma unroll
        for (int j = 0; j < NN; j++) { ex[j] = __expf(logit[tid*NN + j] - m); ssum += ex[j]; }
        float inv = 1.f / ssum;
#pragma unroll
        for (int j = 0; j < NN; j++) logit[tid*NN + j] = ex[j] * inv;
    }
    __syncthreads();

    // ---- aggregate: hag = att @ h, float4 ----
    {
        const float4* h4 = reinterpret_cast<const float4*>(hsm);
        float4* hag4 = reinterpret_cast<float4*>(hag);
        for (int idx = tid; idx < NN*32; idx += 256) {
            int i = idx >> 5;
            int d4 = idx & 31;
            float4 s = make_float4(0.f, 0.f, 0.f, 0.f);
#pragma unroll
            for (int j = 0; j < NN; j++) {
                float w = logit[i*NN + j];
                float4 hv = h4[j*32 + d4];
                s.x += w*hv.x; s.y += w*hv.y; s.z += w*hv.z; s.w += w*hv.w;
            }
            hag4[idx] = s;
        }
    }
    __syncthreads();

    // ---- seq = hag[alias]; hs = masked mean (float4) ----
    {
        const float4* hag4 = reinterpret_cast<const float4*>(hag);
        float4* seq4 = reinterpret_cast<float4*>(&g_seq[(size_t)b*LL*DD]);
        float4 part = make_float4(0.f, 0.f, 0.f, 0.f);
        for (int idx = tid; idx < LL*32; idx += 256) {
            int l = idx >> 5;
            int d4 = idx & 31;
            float4 v = hag4[salias[l]*32 + d4];
            seq4[idx] = v;
            float mf = (float)smask[l];
            part.x += v.x*mf; part.y += v.y*mf; part.z += v.z*mf; part.w += v.w*mf;
        }
        hpart4[tid] = part;
    }
    __syncthreads();
    if (tid < 32) {
        float4 s = make_float4(0.f, 0.f, 0.f, 0.f);
#pragma unroll
        for (int w = 0; w < 8; w++) {
            float4 v = hpart4[tid + 32*w];
            s.x += v.x; s.y += v.y; s.z += v.z; s.w += v.w;
        }
        float inv = 1.f / sdenom;
        s.x *= inv; s.y *= inv; s.z *= inv; s.w *= inv;
        reinterpret_cast<float4*>(&g_hs[(size_t)b*DD])[tid] = s;
    }
}

// ==================== K3h: hsg = glu1_b + hs @ glu2_w ====================
__global__ void k3_hsg(const float* __restrict__ glu2_w, const float* __restrict__ glu1_b) {
    __shared__ float shs[DD];
    int b = blockIdx.x, d = threadIdx.x;
    shs[d] = g_hs[(size_t)b*DD + d];
    __syncthreads();
    float s = glu1_b[d];
    for (int k = 0; k < DD; k++) s += shs[k] * glu2_w[k*DD + d];
    g_hsg[(size_t)b*DD + d] = s;
}

// ==================== K3a: nh = tanh([pos_rev | seq] @ w_1) ====================
__global__ void k3a_nh(const float* __restrict__ pos_emb, const float* __restrict__ w_1) {
    __shared__ float Asm[KT*AST];
    __shared__ float Bsm[KT*BST];
    int tid = threadIdx.x;
    int m0 = blockIdx.x * TM;
    int tc = tid & 15, tr = tid >> 4;
    float acc[4][8] = {};
    for (int kt = 0; kt < 16; kt++) {
        int k0 = kt * KT;
#pragma unroll
        for (int t = 0; t < 4; t++) {
            int idx = tid + t*256;
            int kk = idx & 15, r = idx >> 4;
            int row = m0 + r;
            float a;
            if (k0 < DD) {
                int l = row % LL;
                a = pos_emb[(LL - 1 - l)*DD + k0 + kk];
            } else {
                a = g_seq[(size_t)row*DD + (k0 - DD) + kk];
            }
            Asm[kk*AST + r] = a;
        }
#pragma unroll
        for (int t = 0; t < 8; t++) {
            int idx = tid + t*256;
            int c = idx & 127, kk = idx >> 7;
            Bsm[kk*BST + c] = w_1[(k0 + kk)*DD + c];
        }
        __syncthreads();
        mm_step(Asm, Bsm, acc, tr, tc);
        __syncthreads();
    }
#pragma unroll
    for (int i = 0; i < 4; i++) {
        int row = m0 + tr*4 + i;
#pragma unroll
        for (int j = 0; j < 8; j++) {
            int c = tc*8 + j;
            g_nh[(size_t)row*DD + c] = tanhf(acc[i][j]);
        }
    }
}

// ==================== K3b: gate = sigmoid(nh @ glu1_w + hsg[b]) ====================
__global__ void k3b_gate(const float* __restrict__ glu1_w) {
    __shared__ float Asm[KT*AST];
    __shared__ float Bsm[KT*BST];
    int tid = threadIdx.x;
    int m0 = blockIdx.x * TM;
    int tc = tid & 15, tr = tid >> 4;
    float acc[4][8] = {};
    for (int kt = 0; kt < 8; kt++) {
        int k0 = kt * KT;
#pragma unroll
        for (int t = 0; t < 4; t++) {
            int idx = tid + t*256;
            int kk = idx & 15, r = idx >> 4;
            Asm[kk*AST + r] = g_nh[(size_t)(m0 + r)*DD + k0 + kk];
        }
#pragma unroll
        for (int t = 0; t < 8; t++) {
            int idx = tid + t*256;
            int c = idx & 127, kk = idx >> 7;
            Bsm[kk*BST + c] = glu1_w[(k0 + kk)*DD + c];
        }
        __syncthreads();
        mm_step(Asm, Bsm, acc, tr, tc);
        __syncthreads();
    }
#pragma unroll
    for (int i = 0; i < 4; i++) {
        int row = m0 + tr*4 + i;
        int b = row / LL;
#pragma unroll
        for (int j = 0; j < 8; j++) {
            int c = tc*8 + j;
            float v = acc[i][j] + g_hsg[(size_t)b*DD + c];
            g_gate[(size_t)row*DD + c] = 1.f / (1.f + expf(-v));
        }
    }
}

// ==================== K3c: beta = gate@w_2 ; select = sum_l beta*seq*mask ====================
__global__ void k3c_select(const int* __restrict__ mask_, const float* __restrict__ w_2) {
    __shared__ float beta[LL];
    __shared__ float sw2[DD];
    __shared__ int smask[LL];
    int b = blockIdx.x, tid = threadIdx.x;
    if (tid < DD) sw2[tid] = w_2[tid];
    if (tid < LL) smask[tid] = mask_[b*LL + tid];
    __syncthreads();
    int wid = tid >> 5, lane = tid & 31;
    for (int l = wid; l < LL; l += 8) {
        float s = 0.f;
        const float* g = &g_gate[((size_t)b*LL + l)*DD];
        for (int d = lane; d < DD; d += 32) s += g[d] * sw2[d];
#pragma unroll
        for (int o = 16; o > 0; o >>= 1) s += __shfl_xor_sync(0xffffffffu, s, o);
        if (lane == 0) beta[l] = s;
    }
    __syncthreads();
    if (tid < DD) {
        float s = 0.f;
        for (int l = 0; l < LL; l++)
            s += beta[l] * (float)smask[l] * g_seq[((size_t)b*LL + l)*DD + tid];
        g_select[(size_t)b*DD + tid] = s;
    }
}

// ==================== prep: emb -> padded bf16 hi/lo tiles (K-contiguous) ====================
__global__ void k_prep_B(const float* __restrict__ emb) {
    int idx = blockIdx.x * 256 + threadIdx.x;   // NPAD*64 pair-slots
    if (idx >= NPAD * 64) return;
    int r = idx >> 6;          // padded output-col index n
    int c2 = idx & 63;
    int c = c2 * 2;
    float v0 = 0.f, v1 = 0.f;
    if (r < NV) {
        const float* p = emb + (size_t)(r + 1) * DD + c;
        v0 = p[0]; v1 = p[1];
    }
    u16 h0, l0, h1, l1;
    split_bf16(v0, h0, l0);
    split_bf16(v1, h1, l1);
    u32 hi = (u32)h0 | ((u32)h1 << 16);
    u32 lo = (u32)l0 | ((u32)l1 << 16);
    size_t w = (size_t)(r >> 7) * TILE_U32 + (size_t)(r & 127) * (TSTRIDE/4) + c2;
    reinterpret_cast<u32*>(g_Bhi4)[w] = hi;
    reinterpret_cast<u32*>(g_Blo4)[w] = lo;
}

// ==================== prep: select -> padded bf16 hi/lo tiles ====================
__global__ void k_prep_A() {
    int idx = blockIdx.x * 256 + threadIdx.x;   // 1024*64 pair-slots
    int row = idx >> 6;
    int c2 = idx & 63;
    int c = c2 * 2;
    float v0 = g_select[(size_t)row * DD + c];
    float v1 = g_select[(size_t)row * DD + c + 1];
    u16 h0, l0, h1, l1;
    split_bf16(v0, h0, l0);
    split_bf16(v1, h1, l1);
    u32 hi = (u32)h0 | ((u32)h1 << 16);
    u32 lo = (u32)l0 | ((u32)l1 << 16);
    size_t w = (size_t)(row >> 7) * TILE_U32 + (size_t)(row & 127) * (TSTRIDE/4) + c2;
    reinterpret_cast<u32*>(g_Ahi4)[w] = hi;
    reinterpret_cast<u32*>(g_Alo4)[w] = lo;
}

// ==================== K4: scores GEMM with HMMA (split-bf16, 3 terms) ====================
__global__ void __launch_bounds__(256, 1) k4_mma(float* __restrict__ out) {
    extern __shared__ u8 dsm[];
    int tid = threadIdx.x;
    int wid = tid >> 5;
    int lane = tid & 31;
    int nb = blockIdx.x;   // output-col block (128 cols)
    int mb = blockIdx.y;   // row block (128 rows)

    {
        const uint4* srcs[4] = {
            g_Ahi4 + (size_t)mb * TILE_U4,
            g_Alo4 + (size_t)mb * TILE_U4,
            g_Bhi4 + (size_t)nb * TILE_U4,
            g_Blo4 + (size_t)nb * TILE_U4
        };
        uint4* dsm4 = reinterpret_cast<uint4*>(dsm);
#pragma unroll
        for (int t = 0; t < 4; t++) {
            const uint4* src = srcs[t];
            uint4* dst = dsm4 + t * TILE_U4;
            for (int i = tid; i < TILE_U4; i += 256)
                dst[i] = src[i];
        }
    }
    __syncthreads();

    u32 sbase = smem_u32(dsm);
    u32 sAhi = sbase;
    u32 sAlo = sbase + TILE_BYTES;
    u32 sBhi = sbase + 2*TILE_BYTES;
    u32 sBlo = sbase + 3*TILE_BYTES;

    int mwarp = wid >> 2;        // 0..1
    int nwarp = wid & 3;         // 0..3

    u32 aoff = (u32)(mwarp*64 + (lane & 15)) * TSTRIDE + ((lane >> 4) << 3) * 2;
    u32 boff = (u32)(nwarp*32 + (lane & 7) + ((lane >> 4) << 3)) * TSTRIDE
             + (((lane >> 3) & 1) << 3) * 2;

    float acc[4][4][4];
#pragma unroll
    for (int mi = 0; mi < 4; mi++)
#pragma unroll
        for (int ni = 0; ni < 4; ni++)
#pragma unroll
            for (int q = 0; q < 4; q++) acc[mi][ni][q] = 0.f;

#pragma unroll
    for (int ks = 0; ks < 8; ks++) {
        u32 kbyte = (u32)ks * 32;
        u32 ahi[4][4], alo[4][4], bhi[2][4], blo[2][4];
#pragma unroll
        for (int mi = 0; mi < 4; mi++) {
            u32 off = aoff + (u32)(mi*16)*TSTRIDE + kbyte;
            ldsm4(ahi[mi], sAhi + off);
            ldsm4(alo[mi], sAlo + off);
        }
#pragma unroll
        for (int np = 0; np < 2; np++) {
            u32 off = boff + (u32)(np*16)*TSTRIDE + kbyte;
            ldsm4(bhi[np], sBhi + off);
            ldsm4(blo[np], sBlo + off);
        }
#pragma unroll
        for (int mi = 0; mi < 4; mi++) {
#pragma unroll
            for (int ni = 0; ni < 4; ni++) {
                int np = ni >> 1;
                int s = (ni & 1) * 2;
                mma16816(acc[mi][ni], ahi[mi], bhi[np][s], bhi[np][s+1]);
                mma16816(acc[mi][ni], ahi[mi], blo[np][s], blo[np][s+1]);
                mma16816(acc[mi][ni], alo[mi], bhi[np][s], bhi[np][s+1]);
            }
        }
    }
    __syncthreads();

    float* Csm = reinterpret_cast<float*>(dsm);
    {
        int grp = lane >> 2, qid = lane & 3;
#pragma unroll
        for (int mi = 0; mi < 4; mi++) {
#pragma unroll
            for (int ni = 0; ni < 4; ni++) {
                int r0 = mwarp*64 + mi*16 + grp;
                int c0 = nwarp*32 + ni*8 + qid*2;
                Csm[r0*132 + c0]       = acc[mi][ni][0];
                Csm[r0*132 + c0 + 1]   = acc[mi][ni][1];
                Csm[(r0+8)*132 + c0]   = acc[mi][ni][2];
                Csm[(r0+8)*132 + c0+1] = acc[mi][ni][3];
            }
        }
    }
    __syncthreads();

    {
        int n0 = nb * 128;
        size_t rbase = (size_t)mb * 128;
        for (int i = tid; i < 128*128; i += 256) {
            int r = i >> 7, c = i & 127;
            int gc = n0 + c;
            if (gc < NV)
                out[(rbase + r) * NV + gc] = Csm[r*132 + c];
        }
    }
}

// ==================== host launcher ====================
extern "C" void kernel_launch(void* const* d_in, const int* in_sizes, int n_in,
                              void* d_out, int out_size) {
    const int*   items   = (const int*)  d_in[0];
    const int*   adj     = (const int*)  d_in[1];
    const int*   alias_  = (const int*)  d_in[2];
    const int*   mask_   = (const int*)  d_in[3];
    const float* emb     = (const float*)d_in[4];
    const float* img_emb = (const float*)d_in[5];
    const float* txt_emb = (const float*)d_in[6];
    const float* W_img   = (const float*)d_in[7];
    const float* b_img   = (const float*)d_in[8];
    const float* W_txt   = (const float*)d_in[9];
    const float* b_txt   = (const float*)d_in[10];
    const float* W_fuse  = (const float*)d_in[11];
    const float* b_fuse  = (const float*)d_in[12];
    const float* a_rel   = (const float*)d_in[13];
    const float* pos_emb = (const float*)d_in[14];
    const float* w_1     = (const float*)d_in[15];
    const float* w_2     = (const float*)d_in[16];
    const float* glu1_w  = (const float*)d_in[17];
    const float* glu1_b  = (const float*)d_in[18];
    const float* glu2_w  = (const float*)d_in[19];
    float* out = (float*)d_out;

    cudaFuncSetAttribute(k4_mma, cudaFuncAttributeMaxDynamicSharedMemorySize, SMEM_K4);

    k_prep_B<<<(NPAD*64 + 255)/256, 256>>>(emb);
    k0_combine<<<DD, DD>>>(W_img, W_txt, W_fuse, b_img, b_txt, b_fuse);
    k1_fuse<<<(BB*NN)/TM, 256>>>(items, emb, img_emb, txt_emb, W_fuse);
    k2_attn<<<BB, 256>>>(adj, alias_, mask_, a_rel);
    k3_hsg<<<BB, DD>>>(glu2_w, glu1_b);
    k3a_nh<<<(BB*LL)/TM, 256>>>(pos_emb, w_1);
    k3b_gate<<<(BB*LL)/TM, 256>>>(glu1_w);
    k3c_select<<<BB, 256>>>(mask_, w_2);
    k_prep_A<<<(BB*64)/256, 256>>>();
    dim3 g4(NB4, BB/128);
    k4_mma<<<g4, 256, SMEM_K4>>>(out);
}

// round 9
// speedup vs baseline: 1.9933x; 1.2110x over previous
#include <cuda_runtime.h>
#include <cuda_bf16.h>
#include <cstdint>
#include <math.h>

typedef unsigned char      u8;
typedef unsigned short     u16;
typedef unsigned int       u32;
typedef unsigned long long u64;

// Problem sizes (fixed by reference)
#define BB 1024
#define NN 24
#define LL 24
#define DD 128
#define VV 40000
#define NV 39999      // V-1 output columns
#define ALPHA 0.2f
#define NEGC (-9e15f)

// HMMA tile format
#define NB4 313              // ceil(39999/128)
#define NPAD (NB4*128)       // 40064
#define TROWS 128
#define TSTRIDE 272          // bytes per row (17 x 16B -> conflict-free ldmatrix)
#define TILE_BYTES (TROWS*TSTRIDE)      // 34816
#define TILE_U4 (TILE_BYTES/16)         // 2176
#define TILE_U32 (TILE_BYTES/4)         // 8704
#define SMEM_K4 (4*TILE_BYTES)          // 139264

// -------- device scratch (no runtime allocations allowed) --------
__device__ float g_Wci[DD*DD];
__device__ float g_Wct[DD*DD];
__device__ float g_bcomb[DD];
__device__ float g_h[BB*NN*DD];
__device__ float g_seq[BB*LL*DD];
__device__ float g_nh[BB*LL*DD];
__device__ float g_gate[BB*LL*DD];
__device__ float g_hs[BB*DD];
__device__ float g_hsg[BB*DD];
__device__ float g_select[BB*DD];
// padded bf16 hi/lo tiles
__device__ uint4 g_Bhi4[(size_t)NB4*TILE_U4];
__device__ uint4 g_Blo4[(size_t)NB4*TILE_U4];
__device__ uint4 g_Ahi4[8*TILE_U4];
__device__ uint4 g_Alo4[8*TILE_U4];
// transposed weight tiles for mid GEMMs: [0..2]=k1 (Wfuse0,Wci,Wct), [3..4]=w_1, [5]=glu1_w
__device__ uint4 g_Wt_hi[6*TILE_U4];
__device__ uint4 g_Wt_lo[6*TILE_U4];

// ==================== helpers ====================
__device__ __forceinline__ u32 smem_u32(const void* p) {
    u32 a;
    asm("{ .reg .u64 t; cvta.to.shared.u64 t, %1; cvt.u32.u64 %0, t; }" : "=r"(a) : "l"(p));
    return a;
}
__device__ __forceinline__ void ldsm4(u32* r, u32 addr) {
    asm volatile("ldmatrix.sync.aligned.m8n8.x4.shared.b16 {%0,%1,%2,%3}, [%4];"
        : "=r"(r[0]), "=r"(r[1]), "=r"(r[2]), "=r"(r[3]) : "r"(addr));
}
__device__ __forceinline__ void mma16816(float* c, const u32* a, u32 b0, u32 b1) {
    asm volatile("mma.sync.aligned.m16n8k16.row.col.f32.bf16.bf16.f32 "
        "{%0,%1,%2,%3}, {%4,%5,%6,%7}, {%8,%9}, {%0,%1,%2,%3};"
        : "+f"(c[0]), "+f"(c[1]), "+f"(c[2]), "+f"(c[3])
        : "r"(a[0]), "r"(a[1]), "r"(a[2]), "r"(a[3]), "r"(b0), "r"(b1));
}
__device__ __forceinline__ void split_bf16(float v, u16& h, u16& l) {
    __nv_bfloat16 hb = __float2bfloat16(v);
    float rem = v - __bfloat162float(hb);
    __nv_bfloat16 lb = __float2bfloat16(rem);
    h = __bfloat16_as_ushort(hb);
    l = __bfloat16_as_ushort(lb);
}
__device__ __forceinline__ void split_pair(float v0, float v1, u32& hi, u32& lo) {
    u16 h0, l0, h1, l1;
    split_bf16(v0, h0, l0);
    split_bf16(v1, h1, l1);
    hi = (u32)h0 | ((u32)h1 << 16);
    lo = (u32)l0 | ((u32)l1 << 16);
}

// shared 3-term split-bf16 mainloop over one 128x128xK=128 chunk.
// sA_hi/lo, sW_hi/lo: padded tiles (rows x TSTRIDE bytes).
__device__ __forceinline__ void hmma_chunk(u32 sAhi, u32 sAlo, u32 sBhi, u32 sBlo,
                                           int wid, int lane, float acc[4][4][4]) {
    int mwarp = wid >> 2;
    int nwarp = wid & 3;
    u32 aoff = (u32)(mwarp*64 + (lane & 15)) * TSTRIDE + ((lane >> 4) << 3) * 2;
    u32 boff = (u32)(nwarp*32 + (lane & 7) + ((lane >> 4) << 3)) * TSTRIDE
             + (((lane >> 3) & 1) << 3) * 2;
#pragma unroll
    for (int ks = 0; ks < 8; ks++) {
        u32 kbyte = (u32)ks * 32;
        u32 ahi[4][4], alo[4][4], bhi[2][4], blo[2][4];
#pragma unroll
        for (int mi = 0; mi < 4; mi++) {
            u32 off = aoff + (u32)(mi*16)*TSTRIDE + kbyte;
            ldsm4(ahi[mi], sAhi + off);
            ldsm4(alo[mi], sAlo + off);
        }
#pragma unroll
        for (int np = 0; np < 2; np++) {
            u32 off = boff + (u32)(np*16)*TSTRIDE + kbyte;
            ldsm4(bhi[np], sBhi + off);
            ldsm4(blo[np], sBlo + off);
        }
#pragma unroll
        for (int mi = 0; mi < 4; mi++) {
#pragma unroll
            for (int ni = 0; ni < 4; ni++) {
                int np = ni >> 1;
                int s = (ni & 1) * 2;
                mma16816(acc[mi][ni], ahi[mi], bhi[np][s], bhi[np][s+1]);
                mma16816(acc[mi][ni], ahi[mi], blo[np][s], blo[np][s+1]);
                mma16816(acc[mi][ni], alo[mi], bhi[np][s], bhi[np][s+1]);
            }
        }
    }
}

// ==================== K0: fold W_img/W_txt into W_fuse ====================
__global__ void k0_combine(const float* __restrict__ W_img, const float* __restrict__ W_txt,
                           const float* __restrict__ W_fuse, const float* __restrict__ b_img,
                           const float* __restrict__ b_txt, const float* __restrict__ b_fuse) {
    int k = blockIdx.x, d = threadIdx.x;
    float s1 = 0.f, s2 = 0.f;
    for (int j = 0; j < DD; j++) {
        s1 += W_img[k*DD + j] * W_fuse[(DD   + j)*DD + d];
        s2 += W_txt[k*DD + j] * W_fuse[(2*DD + j)*DD + d];
    }
    g_Wci[k*DD + d] = s1;
    g_Wct[k*DD + d] = s2;
    if (k == 0) {
        float s = b_fuse[d];
        for (int j = 0; j < DD; j++)
            s += b_img[j]*W_fuse[(DD + j)*DD + d] + b_txt[j]*W_fuse[(2*DD + j)*DD + d];
        g_bcomb[d] = s;
    }
}

// ==================== prep: transposed weight tiles (hi/lo) ====================
// tile t, row n (output col), col k: src value W[k][n]
__global__ void k_prep_W(const float* __restrict__ W_fuse, const float* __restrict__ w_1,
                         const float* __restrict__ glu1_w) {
    int idx = blockIdx.x * 256 + threadIdx.x;
    if (idx >= 6*8192) return;
    int t = idx >> 13;
    int n = (idx >> 6) & 127;
    int c2 = idx & 63;
    int k = c2 * 2;
    float v0, v1;
    switch (t) {
        case 0: v0 = W_fuse[k*DD + n];       v1 = W_fuse[(k+1)*DD + n];       break;
        case 1: v0 = g_Wci[k*DD + n];        v1 = g_Wci[(k+1)*DD + n];        break;
        case 2: v0 = g_Wct[k*DD + n];        v1 = g_Wct[(k+1)*DD + n];        break;
        case 3: v0 = w_1[k*DD + n];          v1 = w_1[(k+1)*DD + n];          break;
        case 4: v0 = w_1[(128+k)*DD + n];    v1 = w_1[(128+k+1)*DD + n];      break;
        default: v0 = glu1_w[k*DD + n];      v1 = glu1_w[(k+1)*DD + n];       break;
    }
    u32 hi, lo;
    split_pair(v0, v1, hi, lo);
    size_t w = (size_t)t * TILE_U32 + (size_t)n * (TSTRIDE/4) + c2;
    reinterpret_cast<u32*>(g_Wt_hi)[w] = hi;
    reinterpret_cast<u32*>(g_Wt_lo)[w] = lo;
}

// ==================== k_mid: HMMA GEMM for k1 / k3a / k3b ====================
// mode 0: h = [emb|img|txt gathers] @ W(3 chunks) + bcomb
// mode 1: nh = tanh([pos_rev|seq] @ w_1) (2 chunks)
// mode 2: gate = sigmoid(nh @ glu1_w + hsg[b]) (1 chunk)
__global__ void __launch_bounds__(256, 1) k_mid(int mode,
        const int* __restrict__ items, const float* __restrict__ emb,
        const float* __restrict__ img, const float* __restrict__ txt,
        const float* __restrict__ pos_emb) {
    extern __shared__ u8 dsm[];
    __shared__ int sitem[128];
    int tid = threadIdx.x;
    int wid = tid >> 5, lane = tid & 31;
    int m0 = blockIdx.x * 128;

    if (mode == 0 && tid < 128) sitem[tid] = items[m0 + tid];

    u32 sbase = smem_u32(dsm);
    u32 sAhi = sbase;
    u32 sAlo = sbase + TILE_BYTES;
    u32 sWhi = sbase + 2*TILE_BYTES;
    u32 sWlo = sbase + 3*TILE_BYTES;
    u32* Ahi32 = reinterpret_cast<u32*>(dsm);
    u32* Alo32 = reinterpret_cast<u32*>(dsm + TILE_BYTES);
    uint4* Wh4 = reinterpret_cast<uint4*>(dsm + 2*TILE_BYTES);
    uint4* Wl4 = reinterpret_cast<uint4*>(dsm + 3*TILE_BYTES);

    int nchunks = (mode == 0) ? 3 : (mode == 1) ? 2 : 1;
    int wbase   = (mode == 0) ? 0 : (mode == 1) ? 3 : 5;

    float acc[4][4][4];
#pragma unroll
    for (int mi = 0; mi < 4; mi++)
#pragma unroll
        for (int ni = 0; ni < 4; ni++)
#pragma unroll
            for (int q = 0; q < 4; q++) acc[mi][ni][q] = 0.f;

    for (int t = 0; t < nchunks; t++) {
        if (t > 0) __syncthreads();    // protect smem reuse across chunks
        // weight tiles: linear copy
        {
            const uint4* sh = g_Wt_hi + (size_t)(wbase + t) * TILE_U4;
            const uint4* sl = g_Wt_lo + (size_t)(wbase + t) * TILE_U4;
            for (int i = tid; i < TILE_U4; i += 256) { Wh4[i] = sh[i]; Wl4[i] = sl[i]; }
        }
        // A chunk: fp32 gather -> split-bf16 into padded smem tile
        if (mode == 0) {
            const float* src = (t == 0) ? emb : (t == 1) ? img : txt;
            __syncthreads();   // sitem visible (first chunk) / smem reuse
            for (int idx = tid; idx < 8192; idx += 256) {
                int r = idx >> 6, c2 = idx & 63, c = c2*2;
                const float* p = src + (size_t)sitem[r]*DD + c;
                u32 hi, lo; split_pair(p[0], p[1], hi, lo);
                int w = r*(TSTRIDE/4) + c2;
                Ahi32[w] = hi; Alo32[w] = lo;
            }
        } else if (mode == 1) {
            for (int idx = tid; idx < 8192; idx += 256) {
                int r = idx >> 6, c2 = idx & 63, c = c2*2;
                int row = m0 + r;
                const float* p;
                if (t == 0) { int l = row % LL; p = pos_emb + (size_t)(LL-1-l)*DD + c; }
                else        { p = g_seq + (size_t)row*DD + c; }
                u32 hi, lo; split_pair(p[0], p[1], hi, lo);
                int w = r*(TSTRIDE/4) + c2;
                Ahi32[w] = hi; Alo32[w] = lo;
            }
        } else {
            for (int idx = tid; idx < 8192; idx += 256) {
                int r = idx >> 6, c2 = idx & 63, c = c2*2;
                const float* p = g_nh + (size_t)(m0 + r)*DD + c;
                u32 hi, lo; split_pair(p[0], p[1], hi, lo);
                int w = r*(TSTRIDE/4) + c2;
                Ahi32[w] = hi; Alo32[w] = lo;
            }
        }
        __syncthreads();
        hmma_chunk(sAhi, sAlo, sWhi, sWlo, wid, lane, acc);
    }
    __syncthreads();

    // stage C in smem for coalesced epilogue
    float* Csm = reinterpret_cast<float*>(dsm);
    {
        int mwarp = wid >> 2, nwarp = wid & 3;
        int grp = lane >> 2, qid = lane & 3;
#pragma unroll
        for (int mi = 0; mi < 4; mi++) {
#pragma unroll
            for (int ni = 0; ni < 4; ni++) {
                int r0 = mwarp*64 + mi*16 + grp;
                int c0 = nwarp*32 + ni*8 + qid*2;
                Csm[r0*132 + c0]       = acc[mi][ni][0];
                Csm[r0*132 + c0 + 1]   = acc[mi][ni][1];
                Csm[(r0+8)*132 + c0]   = acc[mi][ni][2];
                Csm[(r0+8)*132 + c0+1] = acc[mi][ni][3];
            }
        }
    }
    __syncthreads();
    for (int i = tid; i < 128*128; i += 256) {
        int r = i >> 7, c = i & 127;
        size_t row = (size_t)(m0 + r);
        float v = Csm[r*132 + c];
        if (mode == 0) {
            g_h[row*DD + c] = v + g_bcomb[c];
        } else if (mode == 1) {
            g_nh[row*DD + c] = tanhf(v);
        } else {
            int b = (int)(row / LL);
            g_gate[row*DD + c] = 1.f / (1.f + expf(-(v + g_hsg[(size_t)b*DD + c])));
        }
    }
}

// ==================== K2: RGAT attention (warp-per-row, register w_r) ====================
__global__ void __launch_bounds__(256) k2_attn(const int* __restrict__ adj,
                        const int* __restrict__ alias_,
                        const int* __restrict__ mask_, const float* __restrict__ a_rel) {
    __shared__ float hsm[NN*DD];
    __shared__ float hag[NN*DD];
    __shared__ float logit[NN*NN];
    __shared__ int sadj[NN*NN];
    __shared__ int salias[LL];
    __shared__ int smask[LL];
    __shared__ float4 hpart4[256];
    __shared__ float sdenom;
    int b = blockIdx.x, tid = threadIdx.x;
    int wid = tid >> 5, lane = tid & 31;

    float4 areg[4];
    {
        const float4* a4 = reinterpret_cast<const float4*>(a_rel);
#pragma unroll
        for (int r = 0; r < 4; r++) areg[r] = a4[r*32 + lane];
    }
    {
        const float4* src = reinterpret_cast<const float4*>(&g_h[(size_t)b*NN*DD]);
        float4* dst = reinterpret_cast<float4*>(hsm);
        for (int i = tid; i < NN*DD/4; i += 256) dst[i] = src[i];
        const int* asrc = adj + (size_t)b*NN*NN;
        for (int i = tid; i < NN*NN; i += 256) sadj[i] = asrc[i];
    }
    if (tid < LL) { salias[tid] = alias_[b*LL + tid]; smask[tid] = mask_[b*LL + tid]; }
    if (tid == 0) {
        int ms = 0;
        for (int l = 0; l < LL; l++) ms += mask_[b*LL + l];
        sdenom = fmaxf((float)ms, 1.f);
    }
    __syncthreads();

    {
        const float4* h4 = reinterpret_cast<const float4*>(hsm);
        for (int i = wid; i < NN; i += 8) {
            float4 hi = h4[i*32 + lane];
            float4 w0, w1, w2, w3;
            w0.x = hi.x*areg[0].x; w0.y = hi.y*areg[0].y; w0.z = hi.z*areg[0].z; w0.w = hi.w*areg[0].w;
            w1.x = hi.x*areg[1].x; w1.y = hi.y*areg[1].y; w1.z = hi.z*areg[1].z; w1.w = hi.w*areg[1].w;
            w2.x = hi.x*areg[2].x; w2.y = hi.y*areg[2].y; w2.z = hi.z*areg[2].z; w2.w = hi.w*areg[2].w;
            w3.x = hi.x*areg[3].x; w3.y = hi.y*areg[3].y; w3.z = hi.z*areg[3].z; w3.w = hi.w*areg[3].w;
#pragma unroll 4
            for (int j = 0; j < NN; j++) {
                float4 hj = h4[j*32 + lane];
                float s0 = w0.x*hj.x + w0.y*hj.y + w0.z*hj.z + w0.w*hj.w;
                float s1 = w1.x*hj.x + w1.y*hj.y + w1.z*hj.z + w1.w*hj.w;
                float s2 = w2.x*hj.x + w2.y*hj.y + w2.z*hj.z + w2.w*hj.w;
                float s3 = w3.x*hj.x + w3.y*hj.y + w3.z*hj.z + w3.w*hj.w;
#pragma unroll
                for (int o = 16; o > 0; o >>= 1) {
                    s0 += __shfl_xor_sync(0xffffffffu, s0, o);
                    s1 += __shfl_xor_sync(0xffffffffu, s1, o);
                    s2 += __shfl_xor_sync(0xffffffffu, s2, o);
                    s3 += __shfl_xor_sync(0xffffffffu, s3, o);
                }
                if (lane == 0) {
                    int r = sadj[i*NN + j];
                    float sv = (r == 1) ? s0 : (r == 2) ? s1 : (r == 3) ? s2 : s3;
                    float e = (sv > 0.f) ? sv : ALPHA * sv;
                    logit[i*NN + j] = (r == 0) ? NEGC : e;
                }
            }
        }
    }
    __syncthreads();

    if (tid < NN) {
        float m = -INFINITY;
#pragma unroll
        for (int j = 0; j < NN; j++) m = fmaxf(m, logit[tid*NN + j]);
        float ex[NN]; float ssum = 0.f;
#pragma unroll
        for (int j = 0; j < NN; j++) { ex[j] = __expf(logit[tid*NN + j] - m); ssum += ex[j]; }
        float inv = 1.f / ssum;
#pragma unroll
        for (int j = 0; j < NN; j++) logit[tid*NN + j] = ex[j] * inv;
    }
    __syncthreads();

    {
        const float4* h4 = reinterpret_cast<const float4*>(hsm);
        float4* hag4 = reinterpret_cast<float4*>(hag);
        for (int idx = tid; idx < NN*32; idx += 256) {
            int i = idx >> 5;
            int d4 = idx & 31;
            float4 s = make_float4(0.f, 0.f, 0.f, 0.f);
#pragma unroll
            for (int j = 0; j < NN; j++) {
                float w = logit[i*NN + j];
                float4 hv = h4[j*32 + d4];
                s.x += w*hv.x; s.y += w*hv.y; s.z += w*hv.z; s.w += w*hv.w;
            }
            hag4[idx] = s;
        }
    }
    __syncthreads();

    {
        const float4* hag4 = reinterpret_cast<const float4*>(hag);
        float4* seq4 = reinterpret_cast<float4*>(&g_seq[(size_t)b*LL*DD]);
        float4 part = make_float4(0.f, 0.f, 0.f, 0.f);
        for (int idx = tid; idx < LL*32; idx += 256) {
            int l = idx >> 5;
            int d4 = idx & 31;
            float4 v = hag4[salias[l]*32 + d4];
            seq4[idx] = v;
            float mf = (float)smask[l];
            part.x += v.x*mf; part.y += v.y*mf; part.z += v.z*mf; part.w += v.w*mf;
        }
        hpart4[tid] = part;
    }
    __syncthreads();
    if (tid < 32) {
        float4 s = make_float4(0.f, 0.f, 0.f, 0.f);
#pragma unroll
        for (int w = 0; w < 8; w++) {
            float4 v = hpart4[tid + 32*w];
            s.x += v.x; s.y += v.y; s.z += v.z; s.w += v.w;
        }
        float inv = 1.f / sdenom;
        s.x *= inv; s.y *= inv; s.z *= inv; s.w *= inv;
        reinterpret_cast<float4*>(&g_hs[(size_t)b*DD])[tid] = s;
    }
}

// ==================== K3h: hsg = glu1_b + hs @ glu2_w ====================
__global__ void k3_hsg(const float* __restrict__ glu2_w, const float* __restrict__ glu1_b) {
    __shared__ float shs[DD];
    int b = blockIdx.x, d = threadIdx.x;
    shs[d] = g_hs[(size_t)b*DD + d];
    __syncthreads();
    float s = glu1_b[d];
    for (int k = 0; k < DD; k++) s += shs[k] * glu2_w[k*DD + d];
    g_hsg[(size_t)b*DD + d] = s;
}

// ==================== K3c: beta = gate@w_2 ; select = sum_l beta*seq*mask ====================
__global__ void k3c_select(const int* __restrict__ mask_, const float* __restrict__ w_2) {
    __shared__ float beta[LL];
    __shared__ float sw2[DD];
    __shared__ int smask[LL];
    int b = blockIdx.x, tid = threadIdx.x;
    if (tid < DD) sw2[tid] = w_2[tid];
    if (tid < LL) smask[tid] = mask_[b*LL + tid];
    __syncthreads();
    int wid = tid >> 5, lane = tid & 31;
    for (int l = wid; l < LL; l += 8) {
        float s = 0.f;
        const float* g = &g_gate[((size_t)b*LL + l)*DD];
        for (int d = lane; d < DD; d += 32) s += g[d] * sw2[d];
#pragma unroll
        for (int o = 16; o > 0; o >>= 1) s += __shfl_xor_sync(0xffffffffu, s, o);
        if (lane == 0) beta[l] = s;
    }
    __syncthreads();
    if (tid < DD) {
        float s = 0.f;
        for (int l = 0; l < LL; l++)
            s += beta[l] * (float)smask[l] * g_seq[((size_t)b*LL + l)*DD + tid];
        g_select[(size_t)b*DD + tid] = s;
    }
}

// ==================== prep: emb -> padded bf16 hi/lo tiles (K-contiguous) ====================
__global__ void k_prep_B(const float* __restrict__ emb) {
    int idx = blockIdx.x * 256 + threadIdx.x;
    if (idx >= NPAD * 64) return;
    int r = idx >> 6;
    int c2 = idx & 63;
    int c = c2 * 2;
    float v0 = 0.f, v1 = 0.f;
    if (r < NV) {
        const float* p = emb + (size_t)(r + 1) * DD + c;
        v0 = p[0]; v1 = p[1];
    }
    u32 hi, lo; split_pair(v0, v1, hi, lo);
    size_t w = (size_t)(r >> 7) * TILE_U32 + (size_t)(r & 127) * (TSTRIDE/4) + c2;
    reinterpret_cast<u32*>(g_Bhi4)[w] = hi;
    reinterpret_cast<u32*>(g_Blo4)[w] = lo;
}

// ==================== prep: select -> padded bf16 hi/lo tiles ====================
__global__ void k_prep_A() {
    int idx = blockIdx.x * 256 + threadIdx.x;
    int row = idx >> 6;
    int c2 = idx & 63;
    int c = c2 * 2;
    float v0 = g_select[(size_t)row * DD + c];
    float v1 = g_select[(size_t)row * DD + c + 1];
    u32 hi, lo; split_pair(v0, v1, hi, lo);
    size_t w = (size_t)(row >> 7) * TILE_U32 + (size_t)(row & 127) * (TSTRIDE/4) + c2;
    reinterpret_cast<u32*>(g_Ahi4)[w] = hi;
    reinterpret_cast<u32*>(g_Alo4)[w] = lo;
}

// ==================== K4: scores GEMM with HMMA (split-bf16, 3 terms) ====================
__global__ void __launch_bounds__(256, 1) k4_mma(float* __restrict__ out) {
    extern __shared__ u8 dsm[];
    int tid = threadIdx.x;
    int wid = tid >> 5;
    int lane = tid & 31;
    int nb = blockIdx.x;
    int mb = blockIdx.y;

    {
        const uint4* srcs[4] = {
            g_Ahi4 + (size_t)mb * TILE_U4,
            g_Alo4 + (size_t)mb * TILE_U4,
            g_Bhi4 + (size_t)nb * TILE_U4,
            g_Blo4 + (size_t)nb * TILE_U4
        };
        uint4* dsm4 = reinterpret_cast<uint4*>(dsm);
#pragma unroll
        for (int t = 0; t < 4; t++) {
            const uint4* src = srcs[t];
            uint4* dst = dsm4 + t * TILE_U4;
            for (int i = tid; i < TILE_U4; i += 256)
                dst[i] = src[i];
        }
    }
    __syncthreads();

    u32 sbase = smem_u32(dsm);
    float acc[4][4][4];
#pragma unroll
    for (int mi = 0; mi < 4; mi++)
#pragma unroll
        for (int ni = 0; ni < 4; ni++)
#pragma unroll
            for (int q = 0; q < 4; q++) acc[mi][ni][q] = 0.f;

    hmma_chunk(sbase, sbase + TILE_BYTES, sbase + 2*TILE_BYTES, sbase + 3*TILE_BYTES,
               wid, lane, acc);
    __syncthreads();

    float* Csm = reinterpret_cast<float*>(dsm);
    {
        int mwarp = wid >> 2, nwarp = wid & 3;
        int grp = lane >> 2, qid = lane & 3;
#pragma unroll
        for (int mi = 0; mi < 4; mi++) {
#pragma unroll
            for (int ni = 0; ni < 4; ni++) {
                int r0 = mwarp*64 + mi*16 + grp;
                int c0 = nwarp*32 + ni*8 + qid*2;
                Csm[r0*132 + c0]       = acc[mi][ni][0];
                Csm[r0*132 + c0 + 1]   = acc[mi][ni][1];
                Csm[(r0+8)*132 + c0]   = acc[mi][ni][2];
                Csm[(r0+8)*132 + c0+1] = acc[mi][ni][3];
            }
        }
    }
    __syncthreads();

    {
        int n0 = nb * 128;
        size_t rbase = (size_t)mb * 128;
        for (int i = tid; i < 128*128; i += 256) {
            int r = i >> 7, c = i & 127;
            int gc = n0 + c;
            if (gc < NV)
                out[(rbase + r) * NV + gc] = Csm[r*132 + c];
        }
    }
}

// ==================== host launcher ====================
extern "C" void kernel_launch(void* const* d_in, const int* in_sizes, int n_in,
                              void* d_out, int out_size) {
    const int*   items   = (const int*)  d_in[0];
    const int*   adj     = (const int*)  d_in[1];
    const int*   alias_  = (const int*)  d_in[2];
    const int*   mask_   = (const int*)  d_in[3];
    const float* emb     = (const float*)d_in[4];
    const float* img_emb = (const float*)d_in[5];
    const float* txt_emb = (const float*)d_in[6];
    const float* W_img   = (const float*)d_in[7];
    const float* b_img   = (const float*)d_in[8];
    const float* W_txt   = (const float*)d_in[9];
    const float* b_txt   = (const float*)d_in[10];
    const float* W_fuse  = (const float*)d_in[11];
    const float* b_fuse  = (const float*)d_in[12];
    const float* a_rel   = (const float*)d_in[13];
    const float* pos_emb = (const float*)d_in[14];
    const float* w_1     = (const float*)d_in[15];
    const float* w_2     = (const float*)d_in[16];
    const float* glu1_w  = (const float*)d_in[17];
    const float* glu1_b  = (const float*)d_in[18];
    const float* glu2_w  = (const float*)d_in[19];
    float* out = (float*)d_out;

    cudaFuncSetAttribute(k4_mma, cudaFuncAttributeMaxDynamicSharedMemorySize, SMEM_K4);
    cudaFuncSetAttribute(k_mid, cudaFuncAttributeMaxDynamicSharedMemorySize, SMEM_K4);

    k_prep_B<<<(NPAD*64 + 255)/256, 256>>>(emb);
    k0_combine<<<DD, DD>>>(W_img, W_txt, W_fuse, b_img, b_txt, b_fuse);
    k_prep_W<<<(6*8192 + 255)/256, 256>>>(W_fuse, w_1, glu1_w);
    k_mid<<<(BB*NN)/128, 256, SMEM_K4>>>(0, items, emb, img_emb, txt_emb, pos_emb);
    k2_attn<<<BB, 256>>>(adj, alias_, mask_, a_rel);
    k3_hsg<<<BB, DD>>>(glu2_w, glu1_b);
    k_mid<<<(BB*LL)/128, 256, SMEM_K4>>>(1, items, emb, img_emb, txt_emb, pos_emb);
    k_mid<<<(BB*LL)/128, 256, SMEM_K4>>>(2, items, emb, img_emb, txt_emb, pos_emb);
    k3c_select<<<BB, 256>>>(mask_, w_2);
    k_prep_A<<<(BB*64)/256, 256>>>();
    dim3 g4(NB4, BB/128);
    k4_mma<<<g4, 256, SMEM_K4>>>(out);
}

// round 12
// speedup vs baseline: 2.2788x; 1.1433x over previous
#include <cuda_runtime.h>
#include <cuda_bf16.h>
#include <cstdint>
#include <math.h>

typedef unsigned char      u8;
typedef unsigned short     u16;
typedef unsigned int       u32;
typedef unsigned long long u64;

// Problem sizes (fixed by reference)
#define BB 1024
#define NN 24
#define LL 24
#define DD 128
#define VV 40000
#define NV 39999      // V-1 output columns
#define ALPHA 0.2f
#define NEGC (-9e15f)

// HMMA tile format
#define NB4 313              // ceil(39999/128) (prep granularity)
#define NB64 625             // ceil(39999/64)  (k4 col blocks)
#define NPAD (NB4*128)       // 40064
#define TSTRIDE 272          // bytes per row (17 x 16B -> conflict-free ldmatrix)
#define TILE_BYTES (128*TSTRIDE)        // 34816 (128-row tile)
#define TILE_U4 (TILE_BYTES/16)         // 2176
#define TILE_U32 (TILE_BYTES/4)         // 8704
#define HTILE_BYTES (64*TSTRIDE)        // 17408 (64-row tile)
#define HTILE_U4 (HTILE_BYTES/16)       // 1088
#define SMEM_HM (2*TILE_BYTES + 2*HTILE_BYTES)   // 104448 -> 2 CTAs/SM

// -------- device scratch (no runtime allocations allowed) --------
__device__ float g_Wci[DD*DD];
__device__ float g_Wct[DD*DD];
__device__ float g_bcomb[DD];
__device__ float g_h[BB*NN*DD];
__device__ float g_seq[BB*LL*DD];
__device__ float g_nh[BB*LL*DD];
__device__ float g_gate[BB*LL*DD];
__device__ float g_hs[BB*DD];
__device__ float g_hsg[BB*DD];
__device__ float g_select[BB*DD];
// padded bf16 hi/lo tiles
__device__ uint4 g_Bhi4[(size_t)NB4*TILE_U4];
__device__ uint4 g_Blo4[(size_t)NB4*TILE_U4];
__device__ uint4 g_Ahi4[8*TILE_U4];
__device__ uint4 g_Alo4[8*TILE_U4];
// transposed weight tiles for mid GEMMs: [0..2]=k1 (Wfuse0,Wci,Wct), [3..4]=w_1, [5]=glu1_w
__device__ uint4 g_Wt_hi[6*TILE_U4];
__device__ uint4 g_Wt_lo[6*TILE_U4];

// ==================== helpers ====================
__device__ __forceinline__ u32 smem_u32(const void* p) {
    u32 a;
    asm("{ .reg .u64 t; cvta.to.shared.u64 t, %1; cvt.u32.u64 %0, t; }" : "=r"(a) : "l"(p));
    return a;
}
__device__ __forceinline__ void ldsm4(u32* r, u32 addr) {
    asm volatile("ldmatrix.sync.aligned.m8n8.x4.shared.b16 {%0,%1,%2,%3}, [%4];"
        : "=r"(r[0]), "=r"(r[1]), "=r"(r[2]), "=r"(r[3]) : "r"(addr));
}
__device__ __forceinline__ void mma16816(float* c, const u32* a, u32 b0, u32 b1) {
    asm volatile("mma.sync.aligned.m16n8k16.row.col.f32.bf16.bf16.f32 "
        "{%0,%1,%2,%3}, {%4,%5,%6,%7}, {%8,%9}, {%0,%1,%2,%3};"
        : "+f"(c[0]), "+f"(c[1]), "+f"(c[2]), "+f"(c[3])
        : "r"(a[0]), "r"(a[1]), "r"(a[2]), "r"(a[3]), "r"(b0), "r"(b1));
}
__device__ __forceinline__ void split_bf16(float v, u16& h, u16& l) {
    __nv_bfloat16 hb = __float2bfloat16(v);
    float rem = v - __bfloat162float(hb);
    __nv_bfloat16 lb = __float2bfloat16(rem);
    h = __bfloat16_as_ushort(hb);
    l = __bfloat16_as_ushort(lb);
}
__device__ __forceinline__ void split_pair(float v0, float v1, u32& hi, u32& lo) {
    u16 h0, l0, h1, l1;
    split_bf16(v0, h0, l0);
    split_bf16(v1, h1, l1);
    hi = (u32)h0 | ((u32)h1 << 16);
    lo = (u32)l0 | ((u32)l1 << 16);
}

// 32x32 warp tile over K=128 chunk, 3-term split-bf16.
// arow: warp row base in A tile; brow: warp row base (output col) in B tile.
__device__ __forceinline__ void hmma_warp32(u32 sAhi, u32 sAlo, u32 sBhi, u32 sBlo,
                                            int arow, int brow, int lane,
                                            float acc[2][4][4]) {
    u32 aoff = (u32)(arow + (lane & 15)) * TSTRIDE + ((lane >> 4) << 3) * 2;
    u32 boff = (u32)(brow + (lane & 7) + ((lane >> 4) << 3)) * TSTRIDE
             + (((lane >> 3) & 1) << 3) * 2;
#pragma unroll
    for (int ks = 0; ks < 8; ks++) {
        u32 kbyte = (u32)ks * 32;
        u32 bhi[2][4], blo[2][4];
#pragma unroll
        for (int np = 0; np < 2; np++) {
            u32 off = boff + (u32)(np*16)*TSTRIDE + kbyte;
            ldsm4(bhi[np], sBhi + off);
            ldsm4(blo[np], sBlo + off);
        }
#pragma unroll
        for (int mi = 0; mi < 2; mi++) {
            u32 ahi[4], alo[4];
            u32 off = aoff + (u32)(mi*16)*TSTRIDE + kbyte;
            ldsm4(ahi, sAhi + off);
            ldsm4(alo, sAlo + off);
#pragma unroll
            for (int ni = 0; ni < 4; ni++) {
                int np = ni >> 1;
                int s = (ni & 1) * 2;
                mma16816(acc[mi][ni], ahi, bhi[np][s], bhi[np][s+1]);
                mma16816(acc[mi][ni], ahi, blo[np][s], blo[np][s+1]);
                mma16816(acc[mi][ni], alo, bhi[np][s], bhi[np][s+1]);
            }
        }
    }
}

// ==================== K0: fold W_img/W_txt into W_fuse ====================
__global__ void k0_combine(const float* __restrict__ W_img, const float* __restrict__ W_txt,
                           const float* __restrict__ W_fuse, const float* __restrict__ b_img,
                           const float* __restrict__ b_txt, const float* __restrict__ b_fuse) {
    int k = blockIdx.x, d = threadIdx.x;
    float s1 = 0.f, s2 = 0.f;
    for (int j = 0; j < DD; j++) {
        s1 += W_img[k*DD + j] * W_fuse[(DD   + j)*DD + d];
        s2 += W_txt[k*DD + j] * W_fuse[(2*DD + j)*DD + d];
    }
    g_Wci[k*DD + d] = s1;
    g_Wct[k*DD + d] = s2;
    if (k == 0) {
        float s = b_fuse[d];
        for (int j = 0; j < DD; j++)
            s += b_img[j]*W_fuse[(DD + j)*DD + d] + b_txt[j]*W_fuse[(2*DD + j)*DD + d];
        g_bcomb[d] = s;
    }
}

// ==================== prep: transposed weight tiles (hi/lo) ====================
__global__ void k_prep_W(const float* __restrict__ W_fuse, const float* __restrict__ w_1,
                         const float* __restrict__ glu1_w) {
    int idx = blockIdx.x * 256 + threadIdx.x;
    if (idx >= 6*8192) return;
    int t = idx >> 13;
    int n = (idx >> 6) & 127;
    int c2 = idx & 63;
    int k = c2 * 2;
    float v0, v1;
    switch (t) {
        case 0: v0 = W_fuse[k*DD + n];       v1 = W_fuse[(k+1)*DD + n];       break;
        case 1: v0 = g_Wci[k*DD + n];        v1 = g_Wci[(k+1)*DD + n];        break;
        case 2: v0 = g_Wct[k*DD + n];        v1 = g_Wct[(k+1)*DD + n];        break;
        case 3: v0 = w_1[k*DD + n];          v1 = w_1[(k+1)*DD + n];          break;
        case 4: v0 = w_1[(128+k)*DD + n];    v1 = w_1[(128+k+1)*DD + n];      break;
        default: v0 = glu1_w[k*DD + n];      v1 = glu1_w[(k+1)*DD + n];       break;
    }
    u32 hi, lo;
    split_pair(v0, v1, hi, lo);
    size_t w = (size_t)t * TILE_U32 + (size_t)n * (TSTRIDE/4) + c2;
    reinterpret_cast<u32*>(g_Wt_hi)[w] = hi;
    reinterpret_cast<u32*>(g_Wt_lo)[w] = lo;
}

// ==================== k_mid: HMMA GEMM (M=64 per CTA) for k1 / k3a / k3b ====================
// mode 0: h = [emb|img|txt gathers] @ W(3 chunks) + bcomb
// mode 1: nh = tanh([pos_rev|seq] @ w_1) (2 chunks)
// mode 2: gate = sigmoid(nh @ glu1_w + hsg[b]) (1 chunk)
__global__ void __launch_bounds__(256, 2) k_mid(int mode,
        const int* __restrict__ items, const float* __restrict__ emb,
        const float* __restrict__ img, const float* __restrict__ txt,
        const float* __restrict__ pos_emb) {
    extern __shared__ u8 dsm[];
    __shared__ int sitem[64];
    int tid = threadIdx.x;
    int wid = tid >> 5, lane = tid & 31;
    int m0 = blockIdx.x * 64;

    if (mode == 0 && tid < 64) sitem[tid] = items[m0 + tid];

    u32 sbase = smem_u32(dsm);
    u32 sAhi = sbase;
    u32 sAlo = sbase + HTILE_BYTES;
    u32 sWhi = sbase + 2*HTILE_BYTES;
    u32 sWlo = sbase + 2*HTILE_BYTES + TILE_BYTES;
    u32* Ahi32 = reinterpret_cast<u32*>(dsm);
    u32* Alo32 = reinterpret_cast<u32*>(dsm + HTILE_BYTES);
    uint4* Wh4 = reinterpret_cast<uint4*>(dsm + 2*HTILE_BYTES);
    uint4* Wl4 = reinterpret_cast<uint4*>(dsm + 2*HTILE_BYTES + TILE_BYTES);

    int nchunks = (mode == 0) ? 3 : (mode == 1) ? 2 : 1;
    int wbase   = (mode == 0) ? 0 : (mode == 1) ? 3 : 5;

    float acc[2][4][4];
#pragma unroll
    for (int mi = 0; mi < 2; mi++)
#pragma unroll
        for (int ni = 0; ni < 4; ni++)
#pragma unroll
            for (int q = 0; q < 4; q++) acc[mi][ni][q] = 0.f;

    __syncthreads();   // sitem visible
    for (int t = 0; t < nchunks; t++) {
        if (t > 0) __syncthreads();    // previous chunk's MMA done before overwrite
        // weight tiles: linear copy (128-row)
        {
            const uint4* sh = g_Wt_hi + (size_t)(wbase + t) * TILE_U4;
            const uint4* sl = g_Wt_lo + (size_t)(wbase + t) * TILE_U4;
            for (int i = tid; i < TILE_U4; i += 256) { Wh4[i] = sh[i]; Wl4[i] = sl[i]; }
        }
        // A chunk: fp32 gather -> split-bf16 into 64-row padded smem tile
        if (mode == 0) {
            const float* src = (t == 0) ? emb : (t == 1) ? img : txt;
            for (int idx = tid; idx < 4096; idx += 256) {
                int r = idx >> 6, c2 = idx & 63, c = c2*2;
                const float* p = src + (size_t)sitem[r]*DD + c;
                u32 hi, lo; split_pair(p[0], p[1], hi, lo);
                int w = r*(TSTRIDE/4) + c2;
                Ahi32[w] = hi; Alo32[w] = lo;
            }
        } else if (mode == 1) {
            for (int idx = tid; idx < 4096; idx += 256) {
                int r = idx >> 6, c2 = idx & 63, c = c2*2;
                int row = m0 + r;
                const float* p;
                if (t == 0) { int l = row % LL; p = pos_emb + (size_t)(LL-1-l)*DD + c; }
                else        { p = g_seq + (size_t)row*DD + c; }
                u32 hi, lo; split_pair(p[0], p[1], hi, lo);
                int w = r*(TSTRIDE/4) + c2;
                Ahi32[w] = hi; Alo32[w] = lo;
            }
        } else {
            for (int idx = tid; idx < 4096; idx += 256) {
                int r = idx >> 6, c2 = idx & 63, c = c2*2;
                const float* p = g_nh + (size_t)(m0 + r)*DD + c;
                u32 hi, lo; split_pair(p[0], p[1], hi, lo);
                int w = r*(TSTRIDE/4) + c2;
                Ahi32[w] = hi; Alo32[w] = lo;
            }
        }
        __syncthreads();
        hmma_warp32(sAhi, sAlo, sWhi, sWlo, (wid >> 2)*32, (wid & 3)*32, lane, acc);
    }
    __syncthreads();

    // stage C (64 x 128, stride 132) for coalesced epilogue
    float* Csm = reinterpret_cast<float*>(dsm);
    {
        int mwarp = wid >> 2, nwarp = wid & 3;
        int grp = lane >> 2, qid = lane & 3;
#pragma unroll
        for (int mi = 0; mi < 2; mi++) {
#pragma unroll
            for (int ni = 0; ni < 4; ni++) {
                int r0 = mwarp*32 + mi*16 + grp;
                int c0 = nwarp*32 + ni*8 + qid*2;
                Csm[r0*132 + c0]       = acc[mi][ni][0];
                Csm[r0*132 + c0 + 1]   = acc[mi][ni][1];
                Csm[(r0+8)*132 + c0]   = acc[mi][ni][2];
                Csm[(r0+8)*132 + c0+1] = acc[mi][ni][3];
            }
        }
    }
    __syncthreads();
    for (int i = tid; i < 64*128; i += 256) {
        int r = i >> 7, c = i & 127;
        size_t row = (size_t)(m0 + r);
        float v = Csm[r*132 + c];
        if (mode == 0) {
            g_h[row*DD + c] = v + g_bcomb[c];
        } else if (mode == 1) {
            g_nh[row*DD + c] = tanhf(v);
        } else {
            int b = (int)(row / LL);
            g_gate[row*DD + c] = 1.f / (1.f + expf(-(v + g_hsg[(size_t)b*DD + c])));
        }
    }
}

// ==================== K2: RGAT attention (warp-per-row, register w_r) ====================
__global__ void __launch_bounds__(256) k2_attn(const int* __restrict__ adj,
                        const int* __restrict__ alias_,
                        const int* __restrict__ mask_, const float* __restrict__ a_rel) {
    __shared__ float hsm[NN*DD];
    __shared__ float hag[NN*DD];
    __shared__ float logit[NN*NN];
    __shared__ int sadj[NN*NN];
    __shared__ int salias[LL];
    __shared__ int smask[LL];
    __shared__ float4 hpart4[256];
    __shared__ float sdenom;
    int b = blockIdx.x, tid = threadIdx.x;
    int wid = tid >> 5, lane = tid & 31;

    float4 areg[4];
    {
        const float4* a4 = reinterpret_cast<const float4*>(a_rel);
#pragma unroll
        for (int r = 0; r < 4; r++) areg[r] = a4[r*32 + lane];
    }
    {
        const float4* src = reinterpret_cast<const float4*>(&g_h[(size_t)b*NN*DD]);
        float4* dst = reinterpret_cast<float4*>(hsm);
        for (int i = tid; i < NN*DD/4; i += 256) dst[i] = src[i];
        const int* asrc = adj + (size_t)b*NN*NN;
        for (int i = tid; i < NN*NN; i += 256) sadj[i] = asrc[i];
    }
    if (tid < LL) { salias[tid] = alias_[b*LL + tid]; smask[tid] = mask_[b*LL + tid]; }
    if (tid == 0) {
        int ms = 0;
        for (int l = 0; l < LL; l++) ms += mask_[b*LL + l];
        sdenom = fmaxf((float)ms, 1.f);
    }
    __syncthreads();

    {
        const float4* h4 = reinterpret_cast<const float4*>(hsm);
        for (int i = wid; i < NN; i += 8) {
            float4 hi = h4[i*32 + lane];
            float4 w0, w1, w2, w3;
            w0.x = hi.x*areg[0].x; w0.y = hi.y*areg[0].y; w0.z = hi.z*areg[0].z; w0.w = hi.w*areg[0].w;
            w1.x = hi.x*areg[1].x; w1.y = hi.y*areg[1].y; w1.z = hi.z*areg[1].z; w1.w = hi.w*areg[1].w;
            w2.x = hi.x*areg[2].x; w2.y = hi.y*areg[2].y; w2.z = hi.z*areg[2].z; w2.w = hi.w*areg[2].w;
            w3.x = hi.x*areg[3].x; w3.y = hi.y*areg[3].y; w3.z = hi.z*areg[3].z; w3.w = hi.w*areg[3].w;
#pragma unroll 4
            for (int j = 0; j < NN; j++) {
                float4 hj = h4[j*32 + lane];
                float s0 = w0.x*hj.x + w0.y*hj.y + w0.z*hj.z + w0.w*hj.w;
                float s1 = w1.x*hj.x + w1.y*hj.y + w1.z*hj.z + w1.w*hj.w;
                float s2 = w2.x*hj.x + w2.y*hj.y + w2.z*hj.z + w2.w*hj.w;
                float s3 = w3.x*hj.x + w3.y*hj.y + w3.z*hj.z + w3.w*hj.w;
#pragma unroll
                for (int o = 16; o > 0; o >>= 1) {
                    s0 += __shfl_xor_sync(0xffffffffu, s0, o);
                    s1 += __shfl_xor_sync(0xffffffffu, s1, o);
                    s2 += __shfl_xor_sync(0xffffffffu, s2, o);
                    s3 += __shfl_xor_sync(0xffffffffu, s3, o);
                }
                if (lane == 0) {
                    int r = sadj[i*NN + j];
                    float sv = (r == 1) ? s0 : (r == 2) ? s1 : (r == 3) ? s2 : s3;
                    float e = (sv > 0.f) ? sv : ALPHA * sv;
                    logit[i*NN + j] = (r == 0) ? NEGC : e;
                }
            }
        }
    }
    __syncthreads();

    if (tid < NN) {
        float m = -INFINITY;
#pragma unroll
        for (int j = 0; j < NN; j++) m = fmaxf(m, logit[tid*NN + j]);
        float ex[NN]; float ssum = 0.f;
#pragma unroll
        for (int j = 0; j < NN; j++) { ex[j] = __expf(logit[tid*NN + j] - m); ssum += ex[j]; }
        float inv = 1.f / ssum;
#pragma unroll
        for (int j = 0; j < NN; j++) logit[tid*NN + j] = ex[j] * inv;
    }
    __syncthreads();

    {
        const float4* h4 = reinterpret_cast<const float4*>(hsm);
        float4* hag4 = reinterpret_cast<float4*>(hag);
        for (int idx = tid; idx < NN*32; idx += 256) {
            int i = idx >> 5;
            int d4 = idx & 31;
            float4 s = make_float4(0.f, 0.f, 0.f, 0.f);
#pragma unroll
            for (int j = 0; j < NN; j++) {
                float w = logit[i*NN + j];
                float4 hv = h4[j*32 + d4];
                s.x += w*hv.x; s.y += w*hv.y; s.z += w*hv.z; s.w += w*hv.w;
            }
            hag4[idx] = s;
        }
    }
    __syncthreads();

    {
        const float4* hag4 = reinterpret_cast<const float4*>(hag);
        float4* seq4 = reinterpret_cast<float4*>(&g_seq[(size_t)b*LL*DD]);
        float4 part = make_float4(0.f, 0.f, 0.f, 0.f);
        for (int idx = tid; idx < LL*32; idx += 256) {
            int l = idx >> 5;
            int d4 = idx & 31;
            float4 v = hag4[salias[l]*32 + d4];
            seq4[idx] = v;
            float mf = (float)smask[l];
            part.x += v.x*mf; part.y += v.y*mf; part.z += v.z*mf; part.w += v.w*mf;
        }
        hpart4[tid] = part;
    }
    __syncthreads();
    if (tid < 32) {
        float4 s = make_float4(0.f, 0.f, 0.f, 0.f);
#pragma unroll
        for (int w = 0; w < 8; w++) {
            float4 v = hpart4[tid + 32*w];
            s.x += v.x; s.y += v.y; s.z += v.z; s.w += v.w;
        }
        float inv = 1.f / sdenom;
        s.x *= inv; s.y *= inv; s.z *= inv; s.w *= inv;
        reinterpret_cast<float4*>(&g_hs[(size_t)b*DD])[tid] = s;
    }
}

// ==================== K3h: hsg = glu1_b + hs @ glu2_w ====================
__global__ void k3_hsg(const float* __restrict__ glu2_w, const float* __restrict__ glu1_b) {
    __shared__ float shs[DD];
    int b = blockIdx.x, d = threadIdx.x;
    shs[d] = g_hs[(size_t)b*DD + d];
    __syncthreads();
    float s = glu1_b[d];
    for (int k = 0; k < DD; k++) s += shs[k] * glu2_w[k*DD + d];
    g_hsg[(size_t)b*DD + d] = s;
}

// ==================== K3c: beta = gate@w_2 ; select = sum_l beta*seq*mask ====================
__global__ void k3c_select(const int* __restrict__ mask_, const float* __restrict__ w_2) {
    __shared__ float beta[LL];
    __shared__ float sw2[DD];
    __shared__ int smask[LL];
    int b = blockIdx.x, tid = threadIdx.x;
    if (tid < DD) sw2[tid] = w_2[tid];
    if (tid < LL) smask[tid] = mask_[b*LL + tid];
    __syncthreads();
    int wid = tid >> 5, lane = tid & 31;
    for (int l = wid; l < LL; l += 8) {
        float s = 0.f;
        const float* g = &g_gate[((size_t)b*LL + l)*DD];
        for (int d = lane; d < DD; d += 32) s += g[d] * sw2[d];
#pragma unroll
        for (int o = 16; o > 0; o >>= 1) s += __shfl_xor_sync(0xffffffffu, s, o);
        if (lane == 0) beta[l] = s;
    }
    __syncthreads();
    if (tid < DD) {
        float s = 0.f;
        for (int l = 0; l < LL; l++)
            s += beta[l] * (float)smask[l] * g_seq[((size_t)b*LL + l)*DD + tid];
        g_select[(size_t)b*DD + tid] = s;
    }
}

// ==================== prep: emb -> padded bf16 hi/lo tiles (K-contiguous) ====================
__global__ void k_prep_B(const float* __restrict__ emb) {
    int idx = blockIdx.x * 256 + threadIdx.x;
    if (idx >= NPAD * 64) return;
    int r = idx >> 6;
    int c2 = idx & 63;
    int c = c2 * 2;
    float v0 = 0.f, v1 = 0.f;
    if (r < NV) {
        const float* p = emb + (size_t)(r + 1) * DD + c;
        v0 = p[0]; v1 = p[1];
    }
    u32 hi, lo; split_pair(v0, v1, hi, lo);
    size_t w = (size_t)(r >> 7) * TILE_U32 + (size_t)(r & 127) * (TSTRIDE/4) + c2;
    reinterpret_cast<u32*>(g_Bhi4)[w] = hi;
    reinterpret_cast<u32*>(g_Blo4)[w] = lo;
}

// ==================== prep: select -> padded bf16 hi/lo tiles ====================
__global__ void k_prep_A() {
    int idx = blockIdx.x * 256 + threadIdx.x;
    int row = idx >> 6;
    int c2 = idx & 63;
    int c = c2 * 2;
    float v0 = g_select[(size_t)row * DD + c];
    float v1 = g_select[(size_t)row * DD + c + 1];
    u32 hi, lo; split_pair(v0, v1, hi, lo);
    size_t w = (size_t)(row >> 7) * TILE_U32 + (size_t)(row & 127) * (TSTRIDE/4) + c2;
    reinterpret_cast<u32*>(g_Ahi4)[w] = hi;
    reinterpret_cast<u32*>(g_Alo4)[w] = lo;
}

// ==================== K4: scores GEMM, 128x64 tile, 2 CTAs/SM ====================
__global__ void __launch_bounds__(256, 2) k4_mma(float* __restrict__ out) {
    extern __shared__ u8 dsm[];
    int tid = threadIdx.x;
    int wid = tid >> 5;
    int lane = tid & 31;
    int nb = blockIdx.x;   // 0..624, 64-col blocks
    int mb = blockIdx.y;   // 0..7, 128-row blocks

    // smem layout: A hi (128r) | A lo (128r) | B hi (64r) | B lo (64r)
    {
        const uint4* sAh = g_Ahi4 + (size_t)mb * TILE_U4;
        const uint4* sAl = g_Alo4 + (size_t)mb * TILE_U4;
        size_t boffg = (size_t)(nb >> 1) * TILE_U4 + (size_t)(nb & 1) * HTILE_U4;
        const uint4* sBh = g_Bhi4 + boffg;
        const uint4* sBl = g_Blo4 + boffg;
        uint4* dsm4 = reinterpret_cast<uint4*>(dsm);
        for (int i = tid; i < TILE_U4; i += 256) {
            dsm4[i] = sAh[i];
            dsm4[TILE_U4 + i] = sAl[i];
        }
        for (int i = tid; i < HTILE_U4; i += 256) {
            dsm4[2*TILE_U4 + i] = sBh[i];
            dsm4[2*TILE_U4 + HTILE_U4 + i] = sBl[i];
        }
    }
    __syncthreads();

    u32 sbase = smem_u32(dsm);
    u32 sAhi = sbase;
    u32 sAlo = sbase + TILE_BYTES;
    u32 sBhi = sbase + 2*TILE_BYTES;
    u32 sBlo = sbase + 2*TILE_BYTES + HTILE_BYTES;

    float acc[2][4][4];
#pragma unroll
    for (int mi = 0; mi < 2; mi++)
#pragma unroll
        for (int ni = 0; ni < 4; ni++)
#pragma unroll
            for (int q = 0; q < 4; q++) acc[mi][ni][q] = 0.f;

    // warp grid 4(m) x 2(n), each warp 32x32
    int mwarp = wid >> 1;        // 0..3
    int nwarp = wid & 1;         // 0..1
    hmma_warp32(sAhi, sAlo, sBhi, sBlo, mwarp*32, nwarp*32, lane, acc);
    __syncthreads();

    // stage C (128 x 64, stride 68) for coalesced writes
    float* Csm = reinterpret_cast<float*>(dsm);
    {
        int grp = lane >> 2, qid = lane & 3;
#pragma unroll
        for (int mi = 0; mi < 2; mi++) {
#pragma unroll
            for (int ni = 0; ni < 4; ni++) {
                int r0 = mwarp*32 + mi*16 + grp;
                int c0 = nwarp*32 + ni*8 + qid*2;
                Csm[r0*68 + c0]       = acc[mi][ni][0];
                Csm[r0*68 + c0 + 1]   = acc[mi][ni][1];
                Csm[(r0+8)*68 + c0]   = acc[mi][ni][2];
                Csm[(r0+8)*68 + c0+1] = acc[mi][ni][3];
            }
        }
    }
    __syncthreads();

    {
        int n0 = nb * 64;
        size_t rbase = (size_t)mb * 128;
        for (int i = tid; i < 128*64; i += 256) {
            int r = i >> 6, c = i & 63;
            int gc = n0 + c;
            if (gc < NV)
                out[(rbase + r) * NV + gc] = Csm[r*68 + c];
        }
    }
}

// ==================== host launcher ====================
extern "C" void kernel_launch(void* const* d_in, const int* in_sizes, int n_in,
                              void* d_out, int out_size) {
    const int*   items   = (const int*)  d_in[0];
    const int*   adj     = (const int*)  d_in[1];
    const int*   alias_  = (const int*)  d_in[2];
    const int*   mask_   = (const int*)  d_in[3];
    const float* emb     = (const float*)d_in[4];
    const float* img_emb = (const float*)d_in[5];
    const float* txt_emb = (const float*)d_in[6];
    const float* W_img   = (const float*)d_in[7];
    const float* b_img   = (const float*)d_in[8];
    const float* W_txt   = (const float*)d_in[9];
    const float* b_txt   = (const float*)d_in[10];
    const float* W_fuse  = (const float*)d_in[11];
    const float* b_fuse  = (const float*)d_in[12];
    const float* a_rel   = (const float*)d_in[13];
    const float* pos_emb = (const float*)d_in[14];
    const float* w_1     = (const float*)d_in[15];
    const float* w_2     = (const float*)d_in[16];
    const float* glu1_w  = (const float*)d_in[17];
    const float* glu1_b  = (const float*)d_in[18];
    const float* glu2_w  = (const float*)d_in[19];
    float* out = (float*)d_out;

    cudaFuncSetAttribute(k4_mma, cudaFuncAttributeMaxDynamicSharedMemorySize, SMEM_HM);
    cudaFuncSetAttribute(k_mid, cudaFuncAttributeMaxDynamicSharedMemorySize, SMEM_HM);

    k_prep_B<<<(NPAD*64 + 255)/256, 256>>>(emb);
    k0_combine<<<DD, DD>>>(W_img, W_txt, W_fuse, b_img, b_txt, b_fuse);
    k_prep_W<<<(6*8192 + 255)/256, 256>>>(W_fuse, w_1, glu1_w);
    k_mid<<<(BB*NN)/64, 256, SMEM_HM>>>(0, items, emb, img_emb, txt_emb, pos_emb);
    k2_attn<<<BB, 256>>>(adj, alias_, mask_, a_rel);
    k3_hsg<<<BB, DD>>>(glu2_w, glu1_b);
    k_mid<<<(BB*LL)/64, 256, SMEM_HM>>>(1, items, emb, img_emb, txt_emb, pos_emb);
    k_mid<<<(BB*LL)/64, 256, SMEM_HM>>>(2, items, emb, img_emb, txt_emb, pos_emb);
    k3c_select<<<BB, 256>>>(mask_, w_2);
    k_prep_A<<<(BB*64)/256, 256>>>();
    dim3 g4(NB64, BB/128);
    k4_mma<<<g4, 256, SMEM_HM>>>(out);
}

// round 14
// speedup vs baseline: 2.3746x; 1.0420x over previous
#include <cuda_runtime.h>
#include <cuda_bf16.h>
#include <cstdint>
#include <math.h>

typedef unsigned char      u8;
typedef unsigned short     u16;
typedef unsigned int       u32;
typedef unsigned long long u64;

// Problem sizes (fixed by reference)
#define BB 1024
#define NN 24
#define LL 24
#define DD 128
#define VV 40000
#define NV 39999      // V-1 output columns
#define ALPHA 0.2f
#define NEGC (-9e15f)

// HMMA tile format
#define NB4 313              // ceil(39999/128) (prep granularity)
#define NB64 625             // ceil(39999/64)  (k4 col blocks)
#define NPAD (NB4*128)       // 40064
#define TSTRIDE 272          // bytes per row (17 x 16B -> conflict-free ldmatrix)
#define TILE_BYTES (128*TSTRIDE)        // 34816 (128-row tile)
#define TILE_U4 (TILE_BYTES/16)         // 2176
#define TILE_U32 (TILE_BYTES/4)         // 8704
#define HTILE_BYTES (64*TSTRIDE)        // 17408 (64-row tile)
#define HTILE_U4 (HTILE_BYTES/16)       // 1088
#define SMEM_HM (2*TILE_BYTES + 2*HTILE_BYTES)   // 104448 -> 2 CTAs/SM

// -------- device scratch (no runtime allocations allowed) --------
__device__ float g_Wci[DD*DD];
__device__ float g_Wct[DD*DD];
__device__ float g_bcomb[DD];
__device__ float g_h[BB*NN*DD];
__device__ float g_seq[BB*LL*DD];
__device__ float g_gate[BB*LL*DD];
__device__ float g_hs[BB*DD];
__device__ float g_hsg[BB*DD];
__device__ float g_select[BB*DD];
// padded bf16 hi/lo tiles
__device__ uint4 g_Bhi4[(size_t)NB4*TILE_U4];
__device__ uint4 g_Blo4[(size_t)NB4*TILE_U4];
__device__ uint4 g_Ahi4[8*TILE_U4];
__device__ uint4 g_Alo4[8*TILE_U4];
// transposed weight tiles for mid GEMMs: [0..2]=k1 (Wfuse0,Wci,Wct), [3..4]=w_1, [5]=glu1_w
__device__ uint4 g_Wt_hi[6*TILE_U4];
__device__ uint4 g_Wt_lo[6*TILE_U4];

// ==================== helpers ====================
__device__ __forceinline__ u32 smem_u32(const void* p) {
    u32 a;
    asm("{ .reg .u64 t; cvta.to.shared.u64 t, %1; cvt.u32.u64 %0, t; }" : "=r"(a) : "l"(p));
    return a;
}
__device__ __forceinline__ void ldsm4(u32* r, u32 addr) {
    asm volatile("ldmatrix.sync.aligned.m8n8.x4.shared.b16 {%0,%1,%2,%3}, [%4];"
        : "=r"(r[0]), "=r"(r[1]), "=r"(r[2]), "=r"(r[3]) : "r"(addr));
}
__device__ __forceinline__ void mma16816(float* c, const u32* a, u32 b0, u32 b1) {
    asm volatile("mma.sync.aligned.m16n8k16.row.col.f32.bf16.bf16.f32 "
        "{%0,%1,%2,%3}, {%4,%5,%6,%7}, {%8,%9}, {%0,%1,%2,%3};"
        : "+f"(c[0]), "+f"(c[1]), "+f"(c[2]), "+f"(c[3])
        : "r"(a[0]), "r"(a[1]), "r"(a[2]), "r"(a[3]), "r"(b0), "r"(b1));
}
__device__ __forceinline__ void split_bf16(float v, u16& h, u16& l) {
    __nv_bfloat16 hb = __float2bfloat16(v);
    float rem = v - __bfloat162float(hb);
    __nv_bfloat16 lb = __float2bfloat16(rem);
    h = __bfloat16_as_ushort(hb);
    l = __bfloat16_as_ushort(lb);
}
__device__ __forceinline__ void split_pair(float v0, float v1, u32& hi, u32& lo) {
    u16 h0, l0, h1, l1;
    split_bf16(v0, h0, l0);
    split_bf16(v1, h1, l1);
    hi = (u32)h0 | ((u32)h1 << 16);
    lo = (u32)l0 | ((u32)l1 << 16);
}

// 32x32 warp tile over K=128 chunk, 3-term split-bf16.
__device__ __forceinline__ void hmma_warp32(u32 sAhi, u32 sAlo, u32 sBhi, u32 sBlo,
                                            int arow, int brow, int lane,
                                            float acc[2][4][4]) {
    u32 aoff = (u32)(arow + (lane & 15)) * TSTRIDE + ((lane >> 4) << 3) * 2;
    u32 boff = (u32)(brow + (lane & 7) + ((lane >> 4) << 3)) * TSTRIDE
             + (((lane >> 3) & 1) << 3) * 2;
#pragma unroll
    for (int ks = 0; ks < 8; ks++) {
        u32 kbyte = (u32)ks * 32;
        u32 bhi[2][4], blo[2][4];
#pragma unroll
        for (int np = 0; np < 2; np++) {
            u32 off = boff + (u32)(np*16)*TSTRIDE + kbyte;
            ldsm4(bhi[np], sBhi + off);
            ldsm4(blo[np], sBlo + off);
        }
#pragma unroll
        for (int mi = 0; mi < 2; mi++) {
            u32 ahi[4], alo[4];
            u32 off = aoff + (u32)(mi*16)*TSTRIDE + kbyte;
            ldsm4(ahi, sAhi + off);
            ldsm4(alo, sAlo + off);
#pragma unroll
            for (int ni = 0; ni < 4; ni++) {
                int np = ni >> 1;
                int s = (ni & 1) * 2;
                mma16816(acc[mi][ni], ahi, bhi[np][s], bhi[np][s+1]);
                mma16816(acc[mi][ni], ahi, blo[np][s], blo[np][s+1]);
                mma16816(acc[mi][ni], alo, bhi[np][s], bhi[np][s+1]);
            }
        }
    }
}

// ==================== K0: fold W_img/W_txt into W_fuse ====================
__global__ void k0_combine(const float* __restrict__ W_img, const float* __restrict__ W_txt,
                           const float* __restrict__ W_fuse, const float* __restrict__ b_img,
                           const float* __restrict__ b_txt, const float* __restrict__ b_fuse) {
    int k = blockIdx.x, d = threadIdx.x;
    float s1 = 0.f, s2 = 0.f;
    for (int j = 0; j < DD; j++) {
        s1 += W_img[k*DD + j] * W_fuse[(DD   + j)*DD + d];
        s2 += W_txt[k*DD + j] * W_fuse[(2*DD + j)*DD + d];
    }
    g_Wci[k*DD + d] = s1;
    g_Wct[k*DD + d] = s2;
    if (k == 0) {
        float s = b_fuse[d];
        for (int j = 0; j < DD; j++)
            s += b_img[j]*W_fuse[(DD + j)*DD + d] + b_txt[j]*W_fuse[(2*DD + j)*DD + d];
        g_bcomb[d] = s;
    }
}

// ==================== prep: transposed weight tiles (hi/lo) ====================
__global__ void k_prep_W(const float* __restrict__ W_fuse, const float* __restrict__ w_1,
                         const float* __restrict__ glu1_w) {
    int idx = blockIdx.x * 256 + threadIdx.x;
    if (idx >= 6*8192) return;
    int t = idx >> 13;
    int n = (idx >> 6) & 127;
    int c2 = idx & 63;
    int k = c2 * 2;
    float v0, v1;
    switch (t) {
        case 0: v0 = W_fuse[k*DD + n];       v1 = W_fuse[(k+1)*DD + n];       break;
        case 1: v0 = g_Wci[k*DD + n];        v1 = g_Wci[(k+1)*DD + n];        break;
        case 2: v0 = g_Wct[k*DD + n];        v1 = g_Wct[(k+1)*DD + n];        break;
        case 3: v0 = w_1[k*DD + n];          v1 = w_1[(k+1)*DD + n];          break;
        case 4: v0 = w_1[(128+k)*DD + n];    v1 = w_1[(128+k+1)*DD + n];      break;
        default: v0 = glu1_w[k*DD + n];      v1 = glu1_w[(k+1)*DD + n];       break;
    }
    u32 hi, lo;
    split_pair(v0, v1, hi, lo);
    size_t w = (size_t)t * TILE_U32 + (size_t)n * (TSTRIDE/4) + c2;
    reinterpret_cast<u32*>(g_Wt_hi)[w] = hi;
    reinterpret_cast<u32*>(g_Wt_lo)[w] = lo;
}

// ==================== k1: fused multimodal embedding (HMMA, M=64/CTA) ====================
__global__ void __launch_bounds__(256, 2) k_mid(
        const int* __restrict__ items, const float* __restrict__ emb,
        const float* __restrict__ img, const float* __restrict__ txt) {
    extern __shared__ u8 dsm[];
    __shared__ int sitem[64];
    int tid = threadIdx.x;
    int wid = tid >> 5, lane = tid & 31;
    int m0 = blockIdx.x * 64;

    if (tid < 64) sitem[tid] = items[m0 + tid];

    u32 sbase = smem_u32(dsm);
    u32 sAhi = sbase;
    u32 sAlo = sbase + HTILE_BYTES;
    u32 sWhi = sbase + 2*HTILE_BYTES;
    u32 sWlo = sbase + 2*HTILE_BYTES + TILE_BYTES;
    u32* Ahi32 = reinterpret_cast<u32*>(dsm);
    u32* Alo32 = reinterpret_cast<u32*>(dsm + HTILE_BYTES);
    uint4* Wh4 = reinterpret_cast<uint4*>(dsm + 2*HTILE_BYTES);
    uint4* Wl4 = reinterpret_cast<uint4*>(dsm + 2*HTILE_BYTES + TILE_BYTES);

    float acc[2][4][4];
#pragma unroll
    for (int mi = 0; mi < 2; mi++)
#pragma unroll
        for (int ni = 0; ni < 4; ni++)
#pragma unroll
            for (int q = 0; q < 4; q++) acc[mi][ni][q] = 0.f;

    __syncthreads();
    for (int t = 0; t < 3; t++) {
        if (t > 0) __syncthreads();
        {
            const uint4* sh = g_Wt_hi + (size_t)t * TILE_U4;
            const uint4* sl = g_Wt_lo + (size_t)t * TILE_U4;
            for (int i = tid; i < TILE_U4; i += 256) { Wh4[i] = sh[i]; Wl4[i] = sl[i]; }
        }
        const float* src = (t == 0) ? emb : (t == 1) ? img : txt;
        for (int idx = tid; idx < 4096; idx += 256) {
            int r = idx >> 6, c2 = idx & 63, c = c2*2;
            const float* p = src + (size_t)sitem[r]*DD + c;
            u32 hi, lo; split_pair(p[0], p[1], hi, lo);
            int w = r*(TSTRIDE/4) + c2;
            Ahi32[w] = hi; Alo32[w] = lo;
        }
        __syncthreads();
        hmma_warp32(sAhi, sAlo, sWhi, sWlo, (wid >> 2)*32, (wid & 3)*32, lane, acc);
    }
    __syncthreads();

    float* Csm = reinterpret_cast<float*>(dsm);
    {
        int mwarp = wid >> 2, nwarp = wid & 3;
        int grp = lane >> 2, qid = lane & 3;
#pragma unroll
        for (int mi = 0; mi < 2; mi++) {
#pragma unroll
            for (int ni = 0; ni < 4; ni++) {
                int r0 = mwarp*32 + mi*16 + grp;
                int c0 = nwarp*32 + ni*8 + qid*2;
                Csm[r0*132 + c0]       = acc[mi][ni][0];
                Csm[r0*132 + c0 + 1]   = acc[mi][ni][1];
                Csm[(r0+8)*132 + c0]   = acc[mi][ni][2];
                Csm[(r0+8)*132 + c0+1] = acc[mi][ni][3];
            }
        }
    }
    __syncthreads();
    for (int i = tid; i < 64*128; i += 256) {
        int r = i >> 7, c = i & 127;
        g_h[(size_t)(m0 + r)*DD + c] = Csm[r*132 + c] + g_bcomb[c];
    }
}

// ==================== k_mid12: fused nh+gate (2 HMMA GEMMs, nh stays in smem) ====================
__global__ void __launch_bounds__(256, 2) k_mid12(const float* __restrict__ pos_emb) {
    extern __shared__ u8 dsm[];
    int tid = threadIdx.x;
    int wid = tid >> 5, lane = tid & 31;
    int m0 = blockIdx.x * 64;

    u32 sbase = smem_u32(dsm);
    u32 sAhi = sbase;
    u32 sAlo = sbase + HTILE_BYTES;
    u32 sWhi = sbase + 2*HTILE_BYTES;
    u32 sWlo = sbase + 2*HTILE_BYTES + TILE_BYTES;
    u32* Ahi32 = reinterpret_cast<u32*>(dsm);
    u32* Alo32 = reinterpret_cast<u32*>(dsm + HTILE_BYTES);
    uint4* Wh4 = reinterpret_cast<uint4*>(dsm + 2*HTILE_BYTES);
    uint4* Wl4 = reinterpret_cast<uint4*>(dsm + 2*HTILE_BYTES + TILE_BYTES);

    int mwarp = wid >> 2, nwarp = wid & 3;
    int grp = lane >> 2, qid = lane & 3;

    float acc[2][4][4];
#pragma unroll
    for (int mi = 0; mi < 2; mi++)
#pragma unroll
        for (int ni = 0; ni < 4; ni++)
#pragma unroll
            for (int q = 0; q < 4; q++) acc[mi][ni][q] = 0.f;

    // ---- GEMM 1: nh_pre = [pos_rev | seq] @ w_1, two K=128 chunks ----
    for (int t = 0; t < 2; t++) {
        if (t > 0) __syncthreads();
        {
            const uint4* sh = g_Wt_hi + (size_t)(3 + t) * TILE_U4;
            const uint4* sl = g_Wt_lo + (size_t)(3 + t) * TILE_U4;
            for (int i = tid; i < TILE_U4; i += 256) { Wh4[i] = sh[i]; Wl4[i] = sl[i]; }
        }
        for (int idx = tid; idx < 4096; idx += 256) {
            int r = idx >> 6, c2 = idx & 63, c = c2*2;
            int row = m0 + r;
            const float* p;
            if (t == 0) { int l = row % LL; p = pos_emb + (size_t)(LL-1-l)*DD + c; }
            else        { p = g_seq + (size_t)row*DD + c; }
            u32 hi, lo; split_pair(p[0], p[1], hi, lo);
            int w = r*(TSTRIDE/4) + c2;
            Ahi32[w] = hi; Alo32[w] = lo;
        }
        __syncthreads();
        hmma_warp32(sAhi, sAlo, sWhi, sWlo, mwarp*32, nwarp*32, lane, acc);
    }
    __syncthreads();   // all MMA reads of A/W done

    // ---- nh = tanh(acc): split-store fragments directly into A slots; load glu1_w ----
    {
#pragma unroll
        for (int mi = 0; mi < 2; mi++) {
#pragma unroll
            for (int ni = 0; ni < 4; ni++) {
                int r0 = mwarp*32 + mi*16 + grp;
                int c2 = (nwarp*32 + ni*8 + qid*2) >> 1;
                u32 hi, lo;
                split_pair(tanhf(acc[mi][ni][0]), tanhf(acc[mi][ni][1]), hi, lo);
                Ahi32[r0*(TSTRIDE/4) + c2] = hi;
                Alo32[r0*(TSTRIDE/4) + c2] = lo;
                split_pair(tanhf(acc[mi][ni][2]), tanhf(acc[mi][ni][3]), hi, lo);
                Ahi32[(r0+8)*(TSTRIDE/4) + c2] = hi;
                Alo32[(r0+8)*(TSTRIDE/4) + c2] = lo;
            }
        }
        const uint4* sh = g_Wt_hi + (size_t)5 * TILE_U4;
        const uint4* sl = g_Wt_lo + (size_t)5 * TILE_U4;
        for (int i = tid; i < TILE_U4; i += 256) { Wh4[i] = sh[i]; Wl4[i] = sl[i]; }
    }
    __syncthreads();

    // ---- GEMM 2: gate_pre = nh @ glu1_w ----
#pragma unroll
    for (int mi = 0; mi < 2; mi++)
#pragma unroll
        for (int ni = 0; ni < 4; ni++)
#pragma unroll
            for (int q = 0; q < 4; q++) acc[mi][ni][q] = 0.f;
    hmma_warp32(sAhi, sAlo, sWhi, sWlo, mwarp*32, nwarp*32, lane, acc);
    __syncthreads();

    // ---- epilogue: gate = sigmoid(acc + hsg[b]) ----
    float* Csm = reinterpret_cast<float*>(dsm);
    {
#pragma unroll
        for (int mi = 0; mi < 2; mi++) {
#pragma unroll
            for (int ni = 0; ni < 4; ni++) {
                int r0 = mwarp*32 + mi*16 + grp;
                int c0 = nwarp*32 + ni*8 + qid*2;
                Csm[r0*132 + c0]       = acc[mi][ni][0];
                Csm[r0*132 + c0 + 1]   = acc[mi][ni][1];
                Csm[(r0+8)*132 + c0]   = acc[mi][ni][2];
                Csm[(r0+8)*132 + c0+1] = acc[mi][ni][3];
            }
        }
    }
    __syncthreads();
    for (int i = tid; i < 64*128; i += 256) {
        int r = i >> 7, c = i & 127;
        size_t row = (size_t)(m0 + r);
        int b = (int)(row / LL);
        float v = Csm[r*132 + c] + g_hsg[(size_t)b*DD + c];
        g_gate[row*DD + c] = 1.f / (1.f + expf(-v));
    }
}

// ==================== K2: RGAT attention (select-first dot + array butterfly) ====================
__global__ void __launch_bounds__(256, 3) k2_attn(const int* __restrict__ adj,
                        const int* __restrict__ alias_,
                        const int* __restrict__ mask_, const float* __restrict__ a_rel) {
    __shared__ float hsm[NN*DD];
    __shared__ float hag[NN*DD];
    __shared__ float logit[NN*NN];
    __shared__ float arel[4*DD];
    __shared__ int sadj[NN*NN];
    __shared__ int salias[LL];
    __shared__ int smask[LL];
    __shared__ float4 hpart4[256];
    __shared__ float sdenom;
    int b = blockIdx.x, tid = threadIdx.x;
    int wid = tid >> 5, lane = tid & 31;

    {
        const float4* src = reinterpret_cast<const float4*>(&g_h[(size_t)b*NN*DD]);
        float4* dst = reinterpret_cast<float4*>(hsm);
        for (int i = tid; i < NN*DD/4; i += 256) dst[i] = src[i];
        const float4* asrc = reinterpret_cast<const float4*>(a_rel);
        float4* adst = reinterpret_cast<float4*>(arel);
        if (tid < 128) adst[tid] = asrc[tid];
        const int* ja = adj + (size_t)b*NN*NN;
        for (int i = tid; i < NN*NN; i += 256) sadj[i] = ja[i];
    }
    if (tid < LL) { salias[tid] = alias_[b*LL + tid]; smask[tid] = mask_[b*LL + tid]; }
    if (tid == 0) {
        int ms = 0;
        for (int l = 0; l < LL; l++) ms += mask_[b*LL + l];
        sdenom = fmaxf((float)ms, 1.f);
    }
    __syncthreads();

    // ---- edge scores: warp per i; select relation first, one dot per j;
    //      per-lane partials accumulate in a register array, then ONE 5-stage
    //      butterfly reduces all 24 j's simultaneously ----
    {
        const float4* h4 = reinterpret_cast<const float4*>(hsm);
        const float4* a4 = reinterpret_cast<const float4*>(arel);
        for (int i = wid; i < NN; i += 8) {
            float4 hi = h4[i*32 + lane];
            float4 a0 = a4[0*32 + lane], a1 = a4[1*32 + lane];
            float4 a2 = a4[2*32 + lane], a3 = a4[3*32 + lane];
            float4 w0, w1, w2, w3;
            w0.x = hi.x*a0.x; w0.y = hi.y*a0.y; w0.z = hi.z*a0.z; w0.w = hi.w*a0.w;
            w1.x = hi.x*a1.x; w1.y = hi.y*a1.y; w1.z = hi.z*a1.z; w1.w = hi.w*a1.w;
            w2.x = hi.x*a2.x; w2.y = hi.y*a2.y; w2.z = hi.z*a2.z; w2.w = hi.w*a2.w;
            w3.x = hi.x*a3.x; w3.y = hi.y*a3.y; w3.z = hi.z*a3.z; w3.w = hi.w*a3.w;
            float part[NN];
#pragma unroll
            for (int j = 0; j < NN; j++) {
                float4 hj = h4[j*32 + lane];
                int r = sadj[i*NN + j];
                float4 ws = (r == 1) ? w0 : (r == 2) ? w1 : (r == 3) ? w2 : w3;
                part[j] = ws.x*hj.x + ws.y*hj.y + ws.z*hj.z + ws.w*hj.w;
            }
#pragma unroll
            for (int off = 16; off > 0; off >>= 1)
#pragma unroll
                for (int j = 0; j < NN; j++)
                    part[j] += __shfl_xor_sync(0xffffffffu, part[j], off);
#pragma unroll
            for (int j = 0; j < NN; j++) {
                if (lane == j) {
                    int r = sadj[i*NN + j];
                    float e = (part[j] > 0.f) ? part[j] : ALPHA * part[j];
                    logit[i*NN + j] = (r == 0) ? NEGC : e;
                }
            }
        }
    }
    __syncthreads();

    // ---- row softmax ----
    if (tid < NN) {
        float m = -INFINITY;
#pragma unroll
        for (int j = 0; j < NN; j++) m = fmaxf(m, logit[tid*NN + j]);
        float ex[NN]; float ssum = 0.f;
#pragma unroll
        for (int j = 0; j < NN; j++) { ex[j] = __expf(logit[tid*NN + j] - m); ssum += ex[j]; }
        float inv = 1.f / ssum;
#pragma unroll
        for (int j = 0; j < NN; j++) logit[tid*NN + j] = ex[j] * inv;
    }
    __syncthreads();

    // ---- aggregate: hag = att @ h ----
    {
        const float4* h4 = reinterpret_cast<const float4*>(hsm);
        float4* hag4 = reinterpret_cast<float4*>(hag);
        for (int idx = tid; idx < NN*32; idx += 256) {
            int i = idx >> 5;
            int d4 = idx & 31;
            float4 s = make_float4(0.f, 0.f, 0.f, 0.f);
#pragma unroll
            for (int j = 0; j < NN; j++) {
                float w = logit[i*NN + j];
                float4 hv = h4[j*32 + d4];
                s.x += w*hv.x; s.y += w*hv.y; s.z += w*hv.z; s.w += w*hv.w;
            }
            hag4[idx] = s;
        }
    }
    __syncthreads();

    // ---- seq = hag[alias]; hs = masked mean ----
    {
        const float4* hag4 = reinterpret_cast<const float4*>(hag);
        float4* seq4 = reinterpret_cast<float4*>(&g_seq[(size_t)b*LL*DD]);
        float4 part = make_float4(0.f, 0.f, 0.f, 0.f);
        for (int idx = tid; idx < LL*32; idx += 256) {
            int l = idx >> 5;
            int d4 = idx & 31;
            float4 v = hag4[salias[l]*32 + d4];
            seq4[idx] = v;
            float mf = (float)smask[l];
            part.x += v.x*mf; part.y += v.y*mf; part.z += v.z*mf; part.w += v.w*mf;
        }
        hpart4[tid] = part;
    }
    __syncthreads();
    if (tid < 32) {
        float4 s = make_float4(0.f, 0.f, 0.f, 0.f);
#pragma unroll
        for (int w = 0; w < 8; w++) {
            float4 v = hpart4[tid + 32*w];
            s.x += v.x; s.y += v.y; s.z += v.z; s.w += v.w;
        }
        float inv = 1.f / sdenom;
        s.x *= inv; s.y *= inv; s.z *= inv; s.w *= inv;
        reinterpret_cast<float4*>(&g_hs[(size_t)b*DD])[tid] = s;
    }
}

// ==================== K3h: hsg = glu1_b + hs @ glu2_w ====================
__global__ void k3_hsg(const float* __restrict__ glu2_w, const float* __restrict__ glu1_b) {
    __shared__ float shs[DD];
    int b = blockIdx.x, d = threadIdx.x;
    shs[d] = g_hs[(size_t)b*DD + d];
    __syncthreads();
    float s = glu1_b[d];
    for (int k = 0; k < DD; k++) s += shs[k] * glu2_w[k*DD + d];
    g_hsg[(size_t)b*DD + d] = s;
}

// ==================== K3c: beta = gate@w_2 ; select = sum_l beta*seq*mask ====================
__global__ void k3c_select(const int* __restrict__ mask_, const float* __restrict__ w_2) {
    __shared__ float beta[LL];
    __shared__ float sw2[DD];
    __shared__ int smask[LL];
    int b = blockIdx.x, tid = threadIdx.x;
    if (tid < DD) sw2[tid] = w_2[tid];
    if (tid < LL) smask[tid] = mask_[b*LL + tid];
    __syncthreads();
    int wid = tid >> 5, lane = tid & 31;
    for (int l = wid; l < LL; l += 8) {
        float s = 0.f;
        const float* g = &g_gate[((size_t)b*LL + l)*DD];
        for (int d = lane; d < DD; d += 32) s += g[d] * sw2[d];
#pragma unroll
        for (int o = 16; o > 0; o >>= 1) s += __shfl_xor_sync(0xffffffffu, s, o);
        if (lane == 0) beta[l] = s;
    }
    __syncthreads();
    if (tid < DD) {
        float s = 0.f;
        for (int l = 0; l < LL; l++)
            s += beta[l] * (float)smask[l] * g_seq[((size_t)b*LL + l)*DD + tid];
        g_select[(size_t)b*DD + tid] = s;
    }
}

// ==================== prep: emb -> padded bf16 hi/lo tiles ====================
__global__ void k_prep_B(const float* __restrict__ emb) {
    int idx = blockIdx.x * 256 + threadIdx.x;
    if (idx >= NPAD * 64) return;
    int r = idx >> 6;
    int c2 = idx & 63;
    int c = c2 * 2;
    float v0 = 0.f, v1 = 0.f;
    if (r < NV) {
        const float* p = emb + (size_t)(r + 1) * DD + c;
        v0 = p[0]; v1 = p[1];
    }
    u32 hi, lo; split_pair(v0, v1, hi, lo);
    size_t w = (size_t)(r >> 7) * TILE_U32 + (size_t)(r & 127) * (TSTRIDE/4) + c2;
    reinterpret_cast<u32*>(g_Bhi4)[w] = hi;
    reinterpret_cast<u32*>(g_Blo4)[w] = lo;
}

// ==================== prep: select -> padded bf16 hi/lo tiles ====================
__global__ void k_prep_A() {
    int idx = blockIdx.x * 256 + threadIdx.x;
    int row = idx >> 6;
    int c2 = idx & 63;
    int c = c2 * 2;
    float v0 = g_select[(size_t)row * DD + c];
    float v1 = g_select[(size_t)row * DD + c + 1];
    u32 hi, lo; split_pair(v0, v1, hi, lo);
    size_t w = (size_t)(row >> 7) * TILE_U32 + (size_t)(row & 127) * (TSTRIDE/4) + c2;
    reinterpret_cast<u32*>(g_Ahi4)[w] = hi;
    reinterpret_cast<u32*>(g_Alo4)[w] = lo;
}

// ==================== K4: scores GEMM, 128x64 tile, 2 CTAs/SM ====================
__global__ void __launch_bounds__(256, 2) k4_mma(float* __restrict__ out) {
    extern __shared__ u8 dsm[];
    int tid = threadIdx.x;
    int wid = tid >> 5;
    int lane = tid & 31;
    int nb = blockIdx.x;
    int mb = blockIdx.y;

    {
        const uint4* sAh = g_Ahi4 + (size_t)mb * TILE_U4;
        const uint4* sAl = g_Alo4 + (size_t)mb * TILE_U4;
        size_t boffg = (size_t)(nb >> 1) * TILE_U4 + (size_t)(nb & 1) * HTILE_U4;
        const uint4* sBh = g_Bhi4 + boffg;
        const uint4* sBl = g_Blo4 + boffg;
        uint4* dsm4 = reinterpret_cast<uint4*>(dsm);
        for (int i = tid; i < TILE_U4; i += 256) {
            dsm4[i] = sAh[i];
            dsm4[TILE_U4 + i] = sAl[i];
        }
        for (int i = tid; i < HTILE_U4; i += 256) {
            dsm4[2*TILE_U4 + i] = sBh[i];
            dsm4[2*TILE_U4 + HTILE_U4 + i] = sBl[i];
        }
    }
    __syncthreads();

    u32 sbase = smem_u32(dsm);
    float acc[2][4][4];
#pragma unroll
    for (int mi = 0; mi < 2; mi++)
#pragma unroll
        for (int ni = 0; ni < 4; ni++)
#pragma unroll
            for (int q = 0; q < 4; q++) acc[mi][ni][q] = 0.f;

    int mwarp = wid >> 1;
    int nwarp = wid & 1;
    hmma_warp32(sbase, sbase + TILE_BYTES, sbase + 2*TILE_BYTES,
                sbase + 2*TILE_BYTES + HTILE_BYTES, mwarp*32, nwarp*32, lane, acc);
    __syncthreads();

    float* Csm = reinterpret_cast<float*>(dsm);
    {
        int grp = lane >> 2, qid = lane & 3;
#pragma unroll
        for (int mi = 0; mi < 2; mi++) {
#pragma unroll
            for (int ni = 0; ni < 4; ni++) {
                int r0 = mwarp*32 + mi*16 + grp;
                int c0 = nwarp*32 + ni*8 + qid*2;
                Csm[r0*68 + c0]       = acc[mi][ni][0];
                Csm[r0*68 + c0 + 1]   = acc[mi][ni][1];
                Csm[(r0+8)*68 + c0]   = acc[mi][ni][2];
                Csm[(r0+8)*68 + c0+1] = acc[mi][ni][3];
            }
        }
    }
    __syncthreads();

    {
        int n0 = nb * 64;
        size_t rbase = (size_t)mb * 128;
        for (int i = tid; i < 128*64; i += 256) {
            int r = i >> 6, c = i & 63;
            int gc = n0 + c;
            if (gc < NV)
                out[(rbase + r) * NV + gc] = Csm[r*68 + c];
        }
    }
}

// ==================== host launcher ====================
extern "C" void kernel_launch(void* const* d_in, const int* in_sizes, int n_in,
                              void* d_out, int out_size) {
    const int*   items   = (const int*)  d_in[0];
    const int*   adj     = (const int*)  d_in[1];
    const int*   alias_  = (const int*)  d_in[2];
    const int*   mask_   = (const int*)  d_in[3];
    const float* emb     = (const float*)d_in[4];
    const float* img_emb = (const float*)d_in[5];
    const float* txt_emb = (const float*)d_in[6];
    const float* W_img   = (const float*)d_in[7];
    const float* b_img   = (const float*)d_in[8];
    const float* W_txt   = (const float*)d_in[9];
    const float* b_txt   = (const float*)d_in[10];
    const float* W_fuse  = (const float*)d_in[11];
    const float* b_fuse  = (const float*)d_in[12];
    const float* a_rel   = (const float*)d_in[13];
    const float* pos_emb = (const float*)d_in[14];
    const float* w_1     = (const float*)d_in[15];
    const float* w_2     = (const float*)d_in[16];
    const float* glu1_w  = (const float*)d_in[17];
    const float* glu1_b  = (const float*)d_in[18];
    const float* glu2_w  = (const float*)d_in[19];
    float* out = (float*)d_out;

    cudaFuncSetAttribute(k4_mma, cudaFuncAttributeMaxDynamicSharedMemorySize, SMEM_HM);
    cudaFuncSetAttribute(k_mid, cudaFuncAttributeMaxDynamicSharedMemorySize, SMEM_HM);
    cudaFuncSetAttribute(k_mid12, cudaFuncAttributeMaxDynamicSharedMemorySize, SMEM_HM);

    k_prep_B<<<(NPAD*64 + 255)/256, 256>>>(emb);
    k0_combine<<<DD, DD>>>(W_img, W_txt, W_fuse, b_img, b_txt, b_fuse);
    k_prep_W<<<(6*8192 + 255)/256, 256>>>(W_fuse, w_1, glu1_w);
    k_mid<<<(BB*NN)/64, 256, SMEM_HM>>>(items, emb, img_emb, txt_emb);
    k2_attn<<<BB, 256>>>(adj, alias_, mask_, a_rel);
    k3_hsg<<<BB, DD>>>(glu2_w, glu1_b);
    k_mid12<<<(BB*LL)/64, 256, SMEM_HM>>>(pos_emb);
    k3c_select<<<BB, 256>>>(mask_, w_2);
    k_prep_A<<<(BB*64)/256, 256>>>();
    dim3 g4(NB64, BB/128);
    k4_mma<<<g4, 256, SMEM_HM>>>(out);
}